// round 2
// baseline (speedup 1.0000x reference)
#include <cuda_runtime.h>
#include <math.h>

#define N_PATCH 676
#define NPAD    704
#define D       384
#define M       200000
#define MPAD    200064
#define TN      64
#define TM      128
#define KB      32
#define NKT     12        // 384/32
#define NBX     11        // ceil(676/64)
#define MBY     1563      // ceil(200000/128)
#define IMG     224
#define KS      33
#define RAD     16

// ---------------- device scratch (no allocations allowed) ----------------
__device__ float g_patchN[NPAD * D];     // normalized patch, zero-padded rows
__device__ float g_pn[NPAD];             // ||p||^2 of normalized rows
__device__ float g_ln[MPAD];             // ||lib_m||^2 (padded rows = 1e30)
__device__ float g_pv[(size_t)NPAD * MBY];  // per-(n, m-block) partial min of ln-2dot
__device__ int   g_pi[(size_t)NPAD * MBY];  // corresponding argmin (global m)
__device__ float g_minval[N_PATCH];
__device__ int   g_minidx[N_PATCH];
__device__ float g_dstar[M];
__device__ float g_rmap[IMG * IMG];
__device__ float g_tmap[IMG * IMG];
__device__ float g_kern[KS];
__device__ int   g_sidx;
__device__ int   g_mstar;
__device__ float g_sstar;
__device__ float g_msn;
__device__ int   g_nn[5];

__device__ __forceinline__ bool lt_vi(float v1, int i1, float v2, int i2) {
    return (v1 < v2) || (v1 == v2 && i1 < i2);
}

// ---------------- 1) normalize patch rows, compute pn ----------------
__global__ void prep_kernel(const float* __restrict__ patch) {
    int n = blockIdx.x, t = threadIdx.x;   // 128 threads
    __shared__ float red[4];
    __shared__ float bcast;
    if (n >= N_PATCH) {
        for (int c = t; c < D; c += 128) g_patchN[(size_t)n * D + c] = 0.f;
        if (t == 0) g_pn[n] = 0.f;
        return;
    }
    float x0 = patch[(size_t)n * D + t];
    float x1 = patch[(size_t)n * D + t + 128];
    float x2 = patch[(size_t)n * D + t + 256];
    float s = x0 * x0 + x1 * x1 + x2 * x2;
    for (int o = 16; o > 0; o >>= 1) s += __shfl_down_sync(0xffffffffu, s, o);
    if ((t & 31) == 0) red[t >> 5] = s;
    __syncthreads();
    if (t == 0) bcast = red[0] + red[1] + red[2] + red[3];
    __syncthreads();
    float inv = 1.f / fmaxf(sqrtf(bcast), 1e-12f);
    float y0 = x0 * inv, y1 = x1 * inv, y2 = x2 * inv;
    g_patchN[(size_t)n * D + t]       = y0;
    g_patchN[(size_t)n * D + t + 128] = y1;
    g_patchN[(size_t)n * D + t + 256] = y2;
    float p = y0 * y0 + y1 * y1 + y2 * y2;
    for (int o = 16; o > 0; o >>= 1) p += __shfl_down_sync(0xffffffffu, p, o);
    if ((t & 31) == 0) red[t >> 5] = p;
    __syncthreads();
    if (t == 0) g_pn[n] = red[0] + red[1] + red[2] + red[3];
}

// ---------------- 2) gaussian kernel weights ----------------
__global__ void gk_kernel() {
    __shared__ float w[KS];
    int t = threadIdx.x;    // 64 threads
    if (t < KS) {
        float x = (float)(t - RAD);
        w[t] = expf(-0.5f * (x / 4.f) * (x / 4.f));
    }
    __syncthreads();
    if (t == 0) {
        float s = 0.f;
        for (int i = 0; i < KS; i++) s += w[i];
        for (int i = 0; i < KS; i++) g_kern[i] = w[i] / s;
    }
}

// ---------------- 3) per-row ||lib||^2 (warp per row, float4) ----------------
__global__ void ln_kernel(const float* __restrict__ lib) {
    int t = threadIdx.x, warp = t >> 5, lane = t & 31;
    long r = (long)blockIdx.x * 8 + warp;
    if (r >= MPAD) return;
    if (r >= M) { if (lane == 0) g_ln[r] = 1e30f; return; }
    const float4* row = (const float4*)(lib + (size_t)r * D);
    float s = 0.f;
#pragma unroll
    for (int j = 0; j < 3; j++) {
        float4 v = row[lane + 32 * j];
        s += v.x * v.x + v.y * v.y + v.z * v.z + v.w * v.w;
    }
    for (int o = 16; o > 0; o >>= 1) s += __shfl_down_sync(0xffffffffu, s, o);
    if (lane == 0) g_ln[r] = s;
}

// ---------------- 4) GEMM + fused per-tile min reduction ----------------
__global__ void __launch_bounds__(128) gemm_kernel(const float* __restrict__ lib) {
    __shared__ float As[KB][TN + 4];   // stride 68 floats: 16B-aligned rows
    __shared__ float Bs[KB][TM + 4];   // stride 132 floats: 16B-aligned rows
    int t = threadIdx.x;
    int tx = t & 15, ty = t >> 4;      // 16 x 8
    int n0 = blockIdx.x * TN;
    int mb = blockIdx.y;
    long m0 = (long)mb * TM;

    float acc[8][8];
#pragma unroll
    for (int i = 0; i < 8; i++)
#pragma unroll
        for (int j = 0; j < 8; j++) acc[i][j] = 0.f;

    for (int kt = 0; kt < NKT; kt++) {
        int k0 = kt * KB;
        // A tile: 64x32 floats = 512 float4, 4 per thread (coalesced)
#pragma unroll
        for (int i = 0; i < 4; i++) {
            int e = i * 128 + t;
            int n = e >> 3, f = e & 7;
            float4 v = *(const float4*)(g_patchN + (size_t)(n0 + n) * D + k0 + f * 4);
            As[f * 4 + 0][n] = v.x; As[f * 4 + 1][n] = v.y;
            As[f * 4 + 2][n] = v.z; As[f * 4 + 3][n] = v.w;
        }
        // B tile: 128x32 floats = 1024 float4, 8 per thread (coalesced)
#pragma unroll
        for (int i = 0; i < 8; i++) {
            int e = i * 128 + t;
            int m = e >> 3, f = e & 7;
            long gm = m0 + m;
            float4 v = (gm < M) ? *(const float4*)(lib + (size_t)gm * D + k0 + f * 4)
                                : make_float4(0.f, 0.f, 0.f, 0.f);
            Bs[f * 4 + 0][m] = v.x; Bs[f * 4 + 1][m] = v.y;
            Bs[f * 4 + 2][m] = v.z; Bs[f * 4 + 3][m] = v.w;
        }
        __syncthreads();
#pragma unroll 8
        for (int k = 0; k < KB; k++) {
            float4 a0 = *(const float4*)&As[k][ty * 8];
            float4 a1 = *(const float4*)&As[k][ty * 8 + 4];
            float4 b0 = *(const float4*)&Bs[k][tx * 4];
            float4 b1 = *(const float4*)&Bs[k][tx * 4 + 64];
            float av[8] = {a0.x, a0.y, a0.z, a0.w, a1.x, a1.y, a1.z, a1.w};
            float bw[8] = {b0.x, b0.y, b0.z, b0.w, b1.x, b1.y, b1.z, b1.w};
#pragma unroll
            for (int i = 0; i < 8; i++)
#pragma unroll
                for (int j = 0; j < 8; j++) acc[i][j] += av[i] * bw[j];
        }
        __syncthreads();
    }
    // epilogue: per-n min of (ln - 2*dot) over this block's 128 m columns
#pragma unroll
    for (int i = 0; i < 8; i++) {
        float bvv = 3.4e38f; int bii = 0x7fffffff;
#pragma unroll
        for (int j = 0; j < 8; j++) {
            long gm = m0 + ((j < 4) ? (tx * 4 + j) : (64 + tx * 4 + (j - 4)));
            float v = g_ln[gm] - 2.f * acc[i][j];
            int idx = (int)gm;
            if (lt_vi(v, idx, bvv, bii)) { bvv = v; bii = idx; }
        }
#pragma unroll
        for (int o = 8; o > 0; o >>= 1) {
            float ov = __shfl_down_sync(0xffffffffu, bvv, o, 16);
            int   oi = __shfl_down_sync(0xffffffffu, bii, o, 16);
            if (lt_vi(ov, oi, bvv, bii)) { bvv = ov; bii = oi; }
        }
        if (tx == 0) {
            int n = n0 + ty * 8 + i;
            g_pv[(size_t)n * MBY + mb] = bvv;
            g_pi[(size_t)n * MBY + mb] = bii;
        }
    }
}

// ---------------- 5) reduce partials -> min_val / min_idx per n ----------------
__global__ void reduce1_kernel() {
    int n = blockIdx.x, t = threadIdx.x;  // 256 threads
    float bv = 3.4e38f; int bi = 0x7fffffff;
    for (int b = t; b < MBY; b += 256) {
        float v = g_pv[(size_t)n * MBY + b];
        int i = g_pi[(size_t)n * MBY + b];
        if (lt_vi(v, i, bv, bi)) { bv = v; bi = i; }
    }
    __shared__ float sv[256]; __shared__ int si[256];
    sv[t] = bv; si[t] = bi;
    __syncthreads();
    for (int s = 128; s > 0; s >>= 1) {
        if (t < s && lt_vi(sv[t + s], si[t + s], sv[t], si[t])) {
            sv[t] = sv[t + s]; si[t] = si[t + s];
        }
        __syncthreads();
    }
    if (t == 0) {
        g_minval[n] = sqrtf(fmaxf(g_pn[n] + sv[0], 0.f));
        g_minidx[n] = si[0];
    }
}

// ---------------- 6) argmax over n; m_star; ||m_star||^2 ----------------
__global__ void reduce2_kernel(const float* __restrict__ lib) {
    int t = threadIdx.x;  // 256
    __shared__ float sv[256]; __shared__ int si[256];
    __shared__ int smstar;
    float bv = -3.4e38f; int bi = 0x7fffffff;
    for (int n = t; n < N_PATCH; n += 256) {
        float v = g_minval[n];
        if (v > bv || (v == bv && n < bi)) { bv = v; bi = n; }
    }
    sv[t] = bv; si[t] = bi;
    __syncthreads();
    for (int s = 128; s > 0; s >>= 1) {
        if (t < s) {
            if (sv[t + s] > sv[t] || (sv[t + s] == sv[t] && si[t + s] < si[t])) {
                sv[t] = sv[t + s]; si[t] = si[t + s];
            }
        }
        __syncthreads();
    }
    if (t == 0) {
        int sidx = si[0];
        g_sidx = sidx;
        g_sstar = sv[0];
        int ms = g_minidx[sidx];
        g_mstar = ms;
        smstar = ms;
    }
    __syncthreads();
    int ms = smstar;
    float p = 0.f;
    for (int c = t; c < D; c += 256) {
        float x = lib[(size_t)ms * D + c];
        p += x * x;
    }
    sv[t] = p; __syncthreads();
    for (int s = 128; s > 0; s >>= 1) { if (t < s) sv[t] += sv[t + s]; __syncthreads(); }
    if (t == 0) g_msn = sv[0];
}

// ---------------- 7) d_star = dist(lib, m_star) ----------------
__global__ void dstar_kernel(const float* __restrict__ lib) {
    __shared__ float4 msv[96];
    int t = threadIdx.x;
    int mi = g_mstar;
    if (t < 96) msv[t] = *((const float4*)(lib + (size_t)mi * D) + t);
    __syncthreads();
    int warp = t >> 5, lane = t & 31;
    long r = (long)blockIdx.x * 8 + warp;
    if (r >= M) return;
    const float4* row = (const float4*)(lib + (size_t)r * D);
    float s = 0.f;
#pragma unroll
    for (int j = 0; j < 3; j++) {
        float4 v = row[lane + 32 * j];
        float4 w = msv[lane + 32 * j];
        s += v.x * w.x + v.y * w.y + v.z * w.z + v.w * w.w;
    }
    for (int o = 16; o > 0; o >>= 1) s += __shfl_down_sync(0xffffffffu, s, o);
    if (lane == 0) g_dstar[r] = sqrtf(fmaxf(g_ln[r] + g_msn - 2.f * s, 0.f));
}

// ---------------- 8) top-5 smallest d_star ----------------
__global__ void top5_kernel() {
    int t = threadIdx.x;  // 256
    float bv[5]; int bi[5];
#pragma unroll
    for (int k = 0; k < 5; k++) { bv[k] = 3.4e38f; bi[k] = 0x7fffffff; }
    for (int m = t; m < M; m += 256) {
        float v = g_dstar[m];
        if (lt_vi(v, m, bv[4], bi[4])) {
            bv[4] = v; bi[4] = m;
#pragma unroll
            for (int k = 4; k > 0; k--) {
                if (lt_vi(bv[k], bi[k], bv[k - 1], bi[k - 1])) {
                    float tv = bv[k]; bv[k] = bv[k - 1]; bv[k - 1] = tv;
                    int ti = bi[k]; bi[k] = bi[k - 1]; bi[k - 1] = ti;
                }
            }
        }
    }
    __shared__ float sv[256][5]; __shared__ int si[256][5];
    __shared__ float rv[256]; __shared__ int ri[256]; __shared__ int rk[256];
#pragma unroll
    for (int k = 0; k < 5; k++) { sv[t][k] = bv[k]; si[t][k] = bi[k]; }
    __syncthreads();
    for (int sel = 0; sel < 5; sel++) {
        float cv = 3.4e38f; int ci = 0x7fffffff; int ck = 0;
#pragma unroll
        for (int k = 0; k < 5; k++)
            if (lt_vi(sv[t][k], si[t][k], cv, ci)) { cv = sv[t][k]; ci = si[t][k]; ck = k; }
        rv[t] = cv; ri[t] = ci; rk[t] = ck * 256 + t;
        __syncthreads();
        for (int s = 128; s > 0; s >>= 1) {
            if (t < s && lt_vi(rv[t + s], ri[t + s], rv[t], ri[t])) {
                rv[t] = rv[t + s]; ri[t] = ri[t + s]; rk[t] = rk[t + s];
            }
            __syncthreads();
        }
        if (t == 0) g_nn[sel] = ri[0];
        int owner = rk[0];
        __syncthreads();
        if (t == (owner & 255)) { sv[t][owner >> 8] = 3.4e38f; si[t][owner >> 8] = 0x7fffffff; }
        __syncthreads();
    }
}

// ---------------- 9) scalar s ----------------
__global__ void scalar_kernel(const float* __restrict__ lib, float* __restrict__ out) {
    __shared__ float dd[6];
    __shared__ int tgt[6];
    int t = threadIdx.x, warp = t >> 5, lane = t & 31;  // 192 threads = 6 warps
    if (t < 5) tgt[t] = g_nn[t];
    if (t == 5) tgt[5] = g_mstar;
    __syncthreads();
    {
        long rm = tgt[warp];
        const float* p = g_patchN + (size_t)g_sidx * D;
        const float* q = lib + (size_t)rm * D;
        float s = 0.f;
        for (int c = lane; c < D; c += 32) {
            float d = p[c] - q[c];
            s += d * d;
        }
        for (int o = 16; o > 0; o >>= 1) s += __shfl_down_sync(0xffffffffu, s, o);
        if (lane == 0) dd[warp] = sqrtf(s);
    }
    __syncthreads();
    if (t == 0) {
        float den = 0.f;
        for (int k = 0; k < 5; k++) den += expf(dd[k]);
        float num = expf(dd[5]);
        out[0] = (1.f - num / den) * g_sstar;
    }
}

// ---------------- 10) bilinear resize 26x26 -> 224x224 (half-pixel) ----------------
__global__ void resize_kernel() {
    int idx = blockIdx.x * 256 + threadIdx.x;
    if (idx >= IMG * IMG) return;
    int y = idx / IMG, x = idx % IMG;
    const float scale = 26.f / 224.f;
    float fy = (y + 0.5f) * scale - 0.5f;
    float fx = (x + 0.5f) * scale - 0.5f;
    int y0 = (int)floorf(fy), x0 = (int)floorf(fx);
    float wy = fy - (float)y0, wx = fx - (float)x0;
    int y0c = min(max(y0, 0), 25), y1c = min(max(y0 + 1, 0), 25);
    int x0c = min(max(x0, 0), 25), x1c = min(max(x0 + 1, 0), 25);
    float v00 = g_minval[y0c * 26 + x0c], v01 = g_minval[y0c * 26 + x1c];
    float v10 = g_minval[y1c * 26 + x0c], v11 = g_minval[y1c * 26 + x1c];
    g_rmap[idx] = (1.f - wy) * ((1.f - wx) * v00 + wx * v01)
                + wy * ((1.f - wx) * v10 + wx * v11);
}

__device__ __forceinline__ int reflect_idx(int i) {
    if (i < 0) return -i;
    if (i > IMG - 1) return 2 * (IMG - 1) - i;
    return i;
}

// ---------------- 11) vertical then horizontal blur (reflect) ----------------
__global__ void blurv_kernel() {
    __shared__ float kw[KS];
    int t = threadIdx.x;
    if (t < KS) kw[t] = g_kern[t];
    __syncthreads();
    int idx = blockIdx.x * 256 + t;
    if (idx >= IMG * IMG) return;
    int y = idx / IMG, x = idx % IMG;
    float s = 0.f;
#pragma unroll
    for (int d = 0; d < KS; d++) {
        int yy = reflect_idx(y + d - RAD);
        s += kw[d] * g_rmap[yy * IMG + x];
    }
    g_tmap[idx] = s;
}

__global__ void blurh_kernel(float* __restrict__ out) {
    __shared__ float kw[KS];
    int t = threadIdx.x;
    if (t < KS) kw[t] = g_kern[t];
    __syncthreads();
    int idx = blockIdx.x * 256 + t;
    if (idx >= IMG * IMG) return;
    int y = idx / IMG, x = idx % IMG;
    float s = 0.f;
#pragma unroll
    for (int d = 0; d < KS; d++) {
        int xx = reflect_idx(x + d - RAD);
        s += kw[d] * g_tmap[y * IMG + xx];
    }
    out[1 + idx] = s;
}

// ---------------- launch ----------------
extern "C" void kernel_launch(void* const* d_in, const int* in_sizes, int n_in,
                              void* d_out, int out_size) {
    const float* patch = (const float*)d_in[0];
    const float* lib   = (const float*)d_in[1];
    if (n_in >= 2 && in_sizes[0] > in_sizes[1]) {  // defensive: patch is the small one
        const float* tmp = patch; patch = lib; lib = tmp;
    }
    float* out = (float*)d_out;

    prep_kernel<<<NPAD, 128>>>(patch);
    gk_kernel<<<1, 64>>>();
    ln_kernel<<<MPAD / 8, 256>>>(lib);
    dim3 gg(NBX, MBY);
    gemm_kernel<<<gg, 128>>>(lib);
    reduce1_kernel<<<N_PATCH, 256>>>();
    reduce2_kernel<<<1, 256>>>(lib);
    dstar_kernel<<<M / 8, 256>>>(lib);
    top5_kernel<<<1, 256>>>();
    scalar_kernel<<<1, 192>>>(lib, out);
    resize_kernel<<<196, 256>>>();
    blurv_kernel<<<196, 256>>>();
    blurh_kernel<<<196, 256>>>(out);
}

// round 4
// speedup vs baseline: 3.1905x; 3.1905x over previous
#include <cuda_runtime.h>
#include <cuda_bf16.h>
#include <math.h>
#include <stdint.h>

#define N_PATCH 676
#define NPAD    768
#define NPT     6          // patch tiles of 128
#define D       384
#define M       200000
#define NTILES  1563       // lib tiles of 128
#define MPAD    (NTILES * 128)
#define NKB     6          // k-blocks of 64
#define IMG     224
#define KS      33
#define RAD     16

__device__ __align__(128) __nv_bfloat16 g_libh[(size_t)MPAD * D];
__device__ __align__(16)  __nv_bfloat16 g_patchh[NPAD * D];
__device__ float g_patchN[NPAD * D];
__device__ float g_pn[NPAD];
__device__ float g_ln[MPAD];
__device__ float g_pv[(size_t)NTILES * NPAD];
__device__ float g_minval[N_PATCH];
__device__ float g_dstar[M];
__device__ float g_rmap[IMG * IMG];
__device__ float g_tmap[IMG * IMG];
__device__ float g_kern[KS];
__device__ int   g_sidx;
__device__ float g_sstar;
__device__ unsigned long long g_argkey;
__device__ int   g_nn[5];

__device__ __forceinline__ uint32_t smem_u32(const void* p) {
    uint32_t a;
    asm("{ .reg .u64 t; cvta.to.shared.u64 t, %1; cvt.u32.u64 %0, t; }" : "=r"(a) : "l"(p));
    return a;
}
#define SW128(x) ((x) ^ (((x) >> 3) & 0x70))

#define CP16(dst, src) asm volatile("cp.async.cg.shared.global [%0], [%1], 16;" :: "r"(dst), "l"(src) : "memory")
#define CP_COMMIT()    asm volatile("cp.async.commit_group;" ::: "memory")
#define CP_WAIT1()     asm volatile("cp.async.wait_group 1;" ::: "memory")
#define CP_WAIT0()     asm volatile("cp.async.wait_group 0;" ::: "memory")

#define LDSM4(r0, r1, r2, r3, addr) \
    asm volatile("ldmatrix.sync.aligned.m8n8.x4.shared.b16 {%0,%1,%2,%3}, [%4];" \
        : "=r"(r0), "=r"(r1), "=r"(r2), "=r"(r3) : "r"(addr))

#define MMA16816(c, a, b0, b1) \
    asm volatile("mma.sync.aligned.m16n8k16.row.col.f32.bf16.bf16.f32 " \
        "{%0,%1,%2,%3}, {%4,%5,%6,%7}, {%8,%9}, {%0,%1,%2,%3};" \
        : "+f"((c)[0]), "+f"((c)[1]), "+f"((c)[2]), "+f"((c)[3]) \
        : "r"((a)[0]), "r"((a)[1]), "r"((a)[2]), "r"((a)[3]), "r"(b0), "r"(b1))

__device__ __forceinline__ bool lt_vi(float v1, int i1, float v2, int i2) {
    return (v1 < v2) || (v1 == v2 && i1 < i2);
}

__device__ __forceinline__ float dot8(uint4 a, uint4 b) {
    const unsigned* pa = (const unsigned*)&a;
    const unsigned* pb = (const unsigned*)&b;
    float s = 0.f;
#pragma unroll
    for (int i = 0; i < 4; i++) {
        float2 fa = __bfloat1622float2(*(const __nv_bfloat162*)&pa[i]);
        float2 fb = __bfloat1622float2(*(const __nv_bfloat162*)&pb[i]);
        s += fa.x * fb.x + fa.y * fb.y;
    }
    return s;
}

// ---------------- 1) normalize patch -> fp32 + bf16, pn ----------------
__global__ void prep_kernel(const float* __restrict__ patch) {
    int n = blockIdx.x, t = threadIdx.x;   // 128 threads
    __shared__ float red[4];
    __shared__ float bcast;
    if (n >= N_PATCH) {
        for (int c = t; c < D; c += 128) {
            g_patchN[(size_t)n * D + c] = 0.f;
            g_patchh[(size_t)n * D + c] = __float2bfloat16(0.f);
        }
        if (t == 0) g_pn[n] = 0.f;
        return;
    }
    float x0 = patch[(size_t)n * D + t];
    float x1 = patch[(size_t)n * D + t + 128];
    float x2 = patch[(size_t)n * D + t + 256];
    float s = x0 * x0 + x1 * x1 + x2 * x2;
    for (int o = 16; o > 0; o >>= 1) s += __shfl_down_sync(0xffffffffu, s, o);
    if ((t & 31) == 0) red[t >> 5] = s;
    __syncthreads();
    if (t == 0) bcast = red[0] + red[1] + red[2] + red[3];
    __syncthreads();
    float inv = 1.f / fmaxf(sqrtf(bcast), 1e-12f);
    float y0 = x0 * inv, y1 = x1 * inv, y2 = x2 * inv;
    g_patchN[(size_t)n * D + t]       = y0;
    g_patchN[(size_t)n * D + t + 128] = y1;
    g_patchN[(size_t)n * D + t + 256] = y2;
    g_patchh[(size_t)n * D + t]       = __float2bfloat16(y0);
    g_patchh[(size_t)n * D + t + 128] = __float2bfloat16(y1);
    g_patchh[(size_t)n * D + t + 256] = __float2bfloat16(y2);
    float p = y0 * y0 + y1 * y1 + y2 * y2;
    for (int o = 16; o > 0; o >>= 1) p += __shfl_down_sync(0xffffffffu, p, o);
    if ((t & 31) == 0) red[t >> 5] = p;
    __syncthreads();
    if (t == 0) g_pn[n] = red[0] + red[1] + red[2] + red[3];
}

// ---------------- 2) lib fp32 -> bf16 + row norms ----------------
__global__ void convert_kernel(const float* __restrict__ lib) {
    int t = threadIdx.x, warp = t >> 5, lane = t & 31;
    long r = (long)blockIdx.x * 8 + warp;
    if (r >= MPAD) return;
    uint2* dst = (uint2*)(g_libh + (size_t)r * D);   // 96 uint2 per row
    if (r >= M) {
        uint2 z = make_uint2(0u, 0u);
        for (int c = lane; c < 96; c += 32) dst[c] = z;
        if (lane == 0) g_ln[r] = 1e30f;
        return;
    }
    const float4* row = (const float4*)(lib + (size_t)r * D);
    float s = 0.f;
#pragma unroll
    for (int j = 0; j < 3; j++) {
        float4 v = row[lane + 32 * j];
        s += v.x * v.x + v.y * v.y + v.z * v.z + v.w * v.w;
        __nv_bfloat162 p0 = __float22bfloat162_rn(make_float2(v.x, v.y));
        __nv_bfloat162 p1 = __float22bfloat162_rn(make_float2(v.z, v.w));
        uint2 o;
        o.x = *reinterpret_cast<unsigned*>(&p0);
        o.y = *reinterpret_cast<unsigned*>(&p1);
        dst[lane + 32 * j] = o;
    }
    for (int o = 16; o > 0; o >>= 1) s += __shfl_down_sync(0xffffffffu, s, o);
    if (lane == 0) g_ln[r] = s;
}

// ---------------- 3) gaussian kernel ----------------
__global__ void gk_kernel() {
    __shared__ float w[KS];
    int t = threadIdx.x;
    if (t < KS) {
        float x = (float)(t - RAD);
        w[t] = expf(-0.5f * (x / 4.f) * (x / 4.f));
    }
    __syncthreads();
    if (t == 0) {
        float s = 0.f;
        for (int i = 0; i < KS; i++) s += w[i];
        for (int i = 0; i < KS; i++) g_kern[i] = w[i] / s;
    }
}

// ---------------- 4) bf16 HMMA GEMM + fused min epilogue ----------------
// CTA: 128 lib rows x 128 patch cols, K blocked by 64, double-buffered cp.async.
// dyn smem: As[2][128][64]bf16 @0/16384, Bs[2][128][64]bf16 @32768/49152 = 64KB.
#define SMEM_DYN 65536

__global__ void __launch_bounds__(256, 2) gemm_bf16() {
    extern __shared__ char dyn[];
    __shared__ float ln_s[128];
    __shared__ float scmb[2][128];

    int t = threadIdx.x;
    int pt = blockIdx.x;       // patch tile (fast -> lib tile L2 reuse)
    int tile = blockIdx.y;     // lib tile
    int lane = t & 31, warp = t >> 5;
    int wm = warp >> 2, wn = warp & 3;

    uint32_t sbase = smem_u32(dyn);
    const char* gA = (const char*)g_libh + (size_t)tile * 128 * 768;
    const char* gB = (const char*)g_patchh + (size_t)pt * 128 * 768;

    if (t < 128) ln_s[t] = g_ln[(size_t)tile * 128 + t];

    // preload k-block 0
#pragma unroll
    for (int i = 0; i < 4; i++) {
        int id = i * 256 + t; int row = id >> 3, seg = id & 7;
        uint32_t off = SW128((uint32_t)(row * 128 + seg * 16));
        CP16(sbase + off, gA + (size_t)row * 768 + seg * 16);
        CP16(sbase + 32768 + off, gB + (size_t)row * 768 + seg * 16);
    }
    CP_COMMIT();

    float c[4][4][4];
#pragma unroll
    for (int mi = 0; mi < 4; mi++)
#pragma unroll
        for (int ni = 0; ni < 4; ni++)
#pragma unroll
            for (int k = 0; k < 4; k++) c[mi][ni][k] = 0.f;

    for (int kb = 0; kb < NKB; kb++) {
        int buf = kb & 1;
        if (kb < NKB - 1) {
            int nb = buf ^ 1;
            const char* ga = gA + (kb + 1) * 128;
            const char* gb = gB + (kb + 1) * 128;
#pragma unroll
            for (int i = 0; i < 4; i++) {
                int id = i * 256 + t; int row = id >> 3, seg = id & 7;
                uint32_t off = SW128((uint32_t)(row * 128 + seg * 16));
                CP16(sbase + nb * 16384 + off, ga + (size_t)row * 768 + seg * 16);
                CP16(sbase + 32768 + nb * 16384 + off, gb + (size_t)row * 768 + seg * 16);
            }
            CP_COMMIT();
            CP_WAIT1();
        } else {
            CP_WAIT0();
        }
        __syncthreads();
        uint32_t sA = sbase + buf * 16384;
        uint32_t sB = sbase + 32768 + buf * 16384;
#pragma unroll
        for (int ks = 0; ks < 4; ks++) {
            uint32_t a[4][4];
#pragma unroll
            for (int mi = 0; mi < 4; mi++) {
                uint32_t byte = (uint32_t)((wm * 64 + mi * 16 + (lane & 15)) * 128
                                           + ks * 32 + (lane >> 4) * 16);
                LDSM4(a[mi][0], a[mi][1], a[mi][2], a[mi][3], sA + SW128(byte));
            }
            uint32_t b[4][2];
#pragma unroll
            for (int nh = 0; nh < 2; nh++) {
                uint32_t byte = (uint32_t)((wn * 32 + nh * 16 + (lane & 15)) * 128
                                           + ks * 32 + (lane >> 4) * 16);
                uint32_t r0, r1, r2, r3;
                LDSM4(r0, r1, r2, r3, sB + SW128(byte));
                b[nh * 2][0] = r0; b[nh * 2 + 1][0] = r1;
                b[nh * 2][1] = r2; b[nh * 2 + 1][1] = r3;
            }
#pragma unroll
            for (int mi = 0; mi < 4; mi++)
#pragma unroll
                for (int ni = 0; ni < 4; ni++)
                    MMA16816(c[mi][ni], a[mi], b[ni][0], b[ni][1]);
        }
        __syncthreads();
    }

    // epilogue: v = ln[row] - 2*dot, min over 128 lib rows per patch col
    float vmin[4][2];
#pragma unroll
    for (int ni = 0; ni < 4; ni++) { vmin[ni][0] = 3.4e38f; vmin[ni][1] = 3.4e38f; }
#pragma unroll
    for (int mi = 0; mi < 4; mi++) {
        float l0 = ln_s[wm * 64 + mi * 16 + (lane >> 2)];
        float l1 = ln_s[wm * 64 + mi * 16 + (lane >> 2) + 8];
#pragma unroll
        for (int ni = 0; ni < 4; ni++) {
            vmin[ni][0] = fminf(vmin[ni][0],
                fminf(fmaf(-2.f, c[mi][ni][0], l0), fmaf(-2.f, c[mi][ni][2], l1)));
            vmin[ni][1] = fminf(vmin[ni][1],
                fminf(fmaf(-2.f, c[mi][ni][1], l0), fmaf(-2.f, c[mi][ni][3], l1)));
        }
    }
#pragma unroll
    for (int off = 4; off < 32; off <<= 1)
#pragma unroll
        for (int ni = 0; ni < 4; ni++) {
            vmin[ni][0] = fminf(vmin[ni][0], __shfl_xor_sync(0xffffffffu, vmin[ni][0], off));
            vmin[ni][1] = fminf(vmin[ni][1], __shfl_xor_sync(0xffffffffu, vmin[ni][1], off));
        }
    if (lane < 4) {
#pragma unroll
        for (int ni = 0; ni < 4; ni++) {
            scmb[wm][wn * 32 + ni * 8 + lane * 2 + 0] = vmin[ni][0];
            scmb[wm][wn * 32 + ni * 8 + lane * 2 + 1] = vmin[ni][1];
        }
    }
    __syncthreads();
    if (t < 128)
        g_pv[(size_t)tile * NPAD + pt * 128 + t] = fminf(scmb[0][t], scmb[1][t]);
}

// ---------------- 5) per-col min over lib tiles -> minval ----------------
__global__ void reduce1_kernel() {
    int pt = blockIdx.x, t = threadIdx.x;  // 6 blocks x 256
    int col = t & 127, half = t >> 7;
    float m = 3.4e38f;
    for (int tile = half; tile < NTILES; tile += 2)
        m = fminf(m, g_pv[(size_t)tile * NPAD + pt * 128 + col]);
    __shared__ float sm[256];
    sm[t] = m;
    __syncthreads();
    if (t < 128) {
        int n = pt * 128 + col;
        if (n < N_PATCH) {
            float v = fminf(sm[t], sm[t + 128]);
            g_minval[n] = sqrtf(fmaxf(g_pn[n] + v, 0.f));
        }
    }
}

// ---------------- 6) argmax over patch rows ----------------
__global__ void argmax_kernel() {
    int t = threadIdx.x;  // 704
    __shared__ float sv[704];
    __shared__ int si[704];
    float val = (t < N_PATCH) ? g_minval[t] : -3.4e38f;
    sv[t] = val; si[t] = t;
    __syncthreads();
    for (int s = 512; s > 0; s >>= 1) {
        if (t < s && t + s < 704) {
            if (sv[t + s] > sv[t] || (sv[t + s] == sv[t] && si[t + s] < si[t])) {
                sv[t] = sv[t + s]; si[t] = si[t + s];
            }
        }
        __syncthreads();
    }
    if (t == 0) {
        g_sidx = si[0];
        g_sstar = sv[0];
        g_argkey = 0xFFFFFFFFFFFFFFFFULL;
    }
}

__device__ __forceinline__ unsigned f2ord(float v) {
    unsigned u = __float_as_uint(v);
    return (u & 0x80000000u) ? ~u : (u | 0x80000000u);
}

// ---------------- 7) argmin over lib for row s_idx ----------------
__global__ void argmin_kernel() {
    __shared__ uint4 q[48];
    __shared__ unsigned long long wk[8];
    int t = threadIdx.x, warp = t >> 5, lane = t & 31;
    if (t < 48) q[t] = ((const uint4*)(g_patchh + (size_t)g_sidx * D))[t];
    __syncthreads();
    long r = (long)blockIdx.x * 8 + warp;
    const uint4* row = (const uint4*)(g_libh + (size_t)r * D);
    float s = dot8(row[lane], q[lane]);
    if (lane < 16) s += dot8(row[32 + lane], q[32 + lane]);
    for (int o = 16; o > 0; o >>= 1) s += __shfl_down_sync(0xffffffffu, s, o);
    if (lane == 0) {
        float v = g_ln[r] - 2.f * s;
        wk[warp] = ((unsigned long long)f2ord(v) << 32) | (unsigned)r;
    }
    __syncthreads();
    if (t == 0) {
        unsigned long long k = wk[0];
        for (int i = 1; i < 8; i++) k = min(k, wk[i]);
        atomicMin(&g_argkey, k);
    }
}

// ---------------- 8) d_star ----------------
__global__ void dstar_kernel() {
    __shared__ uint4 q[48];
    __shared__ float s_msn;
    int t = threadIdx.x, warp = t >> 5, lane = t & 31;
    int mstar = (int)(g_argkey & 0xFFFFFFFFULL);
    if (t < 48) q[t] = ((const uint4*)(g_libh + (size_t)mstar * D))[t];
    if (t == 48) s_msn = g_ln[mstar];
    __syncthreads();
    long r = (long)blockIdx.x * 8 + warp;
    const uint4* row = (const uint4*)(g_libh + (size_t)r * D);
    float s = dot8(row[lane], q[lane]);
    if (lane < 16) s += dot8(row[32 + lane], q[32 + lane]);
    for (int o = 16; o > 0; o >>= 1) s += __shfl_down_sync(0xffffffffu, s, o);
    if (lane == 0) g_dstar[r] = sqrtf(fmaxf(g_ln[r] + s_msn - 2.f * s, 0.f));
}

// ---------------- 9) top-5 smallest d_star ----------------
__global__ void top5_kernel() {
    int t = threadIdx.x;  // 256
    float bv[5]; int bi[5];
#pragma unroll
    for (int k = 0; k < 5; k++) { bv[k] = 3.4e38f; bi[k] = 0x7fffffff; }
    for (int m = t; m < M; m += 256) {
        float v = g_dstar[m];
        if (lt_vi(v, m, bv[4], bi[4])) {
            bv[4] = v; bi[4] = m;
#pragma unroll
            for (int k = 4; k > 0; k--) {
                if (lt_vi(bv[k], bi[k], bv[k - 1], bi[k - 1])) {
                    float tv = bv[k]; bv[k] = bv[k - 1]; bv[k - 1] = tv;
                    int ti = bi[k]; bi[k] = bi[k - 1]; bi[k - 1] = ti;
                }
            }
        }
    }
    __shared__ float sv[256][5]; __shared__ int si[256][5];
    __shared__ float rv[256]; __shared__ int ri[256]; __shared__ int rk[256];
#pragma unroll
    for (int k = 0; k < 5; k++) { sv[t][k] = bv[k]; si[t][k] = bi[k]; }
    __syncthreads();
    for (int sel = 0; sel < 5; sel++) {
        float cv = 3.4e38f; int ci = 0x7fffffff; int ck = 0;
#pragma unroll
        for (int k = 0; k < 5; k++)
            if (lt_vi(sv[t][k], si[t][k], cv, ci)) { cv = sv[t][k]; ci = si[t][k]; ck = k; }
        rv[t] = cv; ri[t] = ci; rk[t] = ck * 256 + t;
        __syncthreads();
        for (int s = 128; s > 0; s >>= 1) {
            if (t < s && lt_vi(rv[t + s], ri[t + s], rv[t], ri[t])) {
                rv[t] = rv[t + s]; ri[t] = ri[t + s]; rk[t] = rk[t + s];
            }
            __syncthreads();
        }
        if (t == 0) g_nn[sel] = ri[0];
        int owner = rk[0];
        __syncthreads();
        if (t == (owner & 255)) { sv[t][owner >> 8] = 3.4e38f; si[t][owner >> 8] = 0x7fffffff; }
        __syncthreads();
    }
}

// ---------------- 10) scalar s (fp32) ----------------
__global__ void scalar_kernel(const float* __restrict__ lib, float* __restrict__ out) {
    __shared__ float dd[6];
    __shared__ int tgt[6];
    int t = threadIdx.x, warp = t >> 5, lane = t & 31;  // 192 threads
    if (t < 5) tgt[t] = g_nn[t];
    if (t == 5) tgt[5] = (int)(g_argkey & 0xFFFFFFFFULL);
    __syncthreads();
    {
        long rm = tgt[warp];
        const float* p = g_patchN + (size_t)g_sidx * D;
        const float* q = lib + (size_t)rm * D;
        float s = 0.f;
        for (int c = lane; c < D; c += 32) {
            float d = p[c] - q[c];
            s += d * d;
        }
        for (int o = 16; o > 0; o >>= 1) s += __shfl_down_sync(0xffffffffu, s, o);
        if (lane == 0) dd[warp] = sqrtf(s);
    }
    __syncthreads();
    if (t == 0) {
        float den = 0.f;
        for (int k = 0; k < 5; k++) den += expf(dd[k]);
        float num = expf(dd[5]);
        out[0] = (1.f - num / den) * g_sstar;
    }
}

// ---------------- 11) bilinear 26->224 ----------------
__global__ void resize_kernel() {
    int idx = blockIdx.x * 256 + threadIdx.x;
    if (idx >= IMG * IMG) return;
    int y = idx / IMG, x = idx % IMG;
    const float scale = 26.f / 224.f;
    float fy = (y + 0.5f) * scale - 0.5f;
    float fx = (x + 0.5f) * scale - 0.5f;
    int y0 = (int)floorf(fy), x0 = (int)floorf(fx);
    float wy = fy - (float)y0, wx = fx - (float)x0;
    int y0c = min(max(y0, 0), 25), y1c = min(max(y0 + 1, 0), 25);
    int x0c = min(max(x0, 0), 25), x1c = min(max(x0 + 1, 0), 25);
    float v00 = g_minval[y0c * 26 + x0c], v01 = g_minval[y0c * 26 + x1c];
    float v10 = g_minval[y1c * 26 + x0c], v11 = g_minval[y1c * 26 + x1c];
    g_rmap[idx] = (1.f - wy) * ((1.f - wx) * v00 + wx * v01)
                + wy * ((1.f - wx) * v10 + wx * v11);
}

__device__ __forceinline__ int reflect_idx(int i) {
    if (i < 0) return -i;
    if (i > IMG - 1) return 2 * (IMG - 1) - i;
    return i;
}

__global__ void blurv_kernel() {
    __shared__ float kw[KS];
    int t = threadIdx.x;
    if (t < KS) kw[t] = g_kern[t];
    __syncthreads();
    int idx = blockIdx.x * 256 + t;
    if (idx >= IMG * IMG) return;
    int y = idx / IMG, x = idx % IMG;
    float s = 0.f;
#pragma unroll
    for (int d = 0; d < KS; d++)
        s += kw[d] * g_rmap[reflect_idx(y + d - RAD) * IMG + x];
    g_tmap[idx] = s;
}

__global__ void blurh_kernel(float* __restrict__ out) {
    __shared__ float kw[KS];
    int t = threadIdx.x;
    if (t < KS) kw[t] = g_kern[t];
    __syncthreads();
    int idx = blockIdx.x * 256 + t;
    if (idx >= IMG * IMG) return;
    int y = idx / IMG, x = idx % IMG;
    float s = 0.f;
#pragma unroll
    for (int d = 0; d < KS; d++)
        s += kw[d] * g_tmap[y * IMG + reflect_idx(x + d - RAD)];
    out[1 + idx] = s;
}

// ---------------- launch ----------------
extern "C" void kernel_launch(void* const* d_in, const int* in_sizes, int n_in,
                              void* d_out, int out_size) {
    const float* patch = (const float*)d_in[0];
    const float* lib   = (const float*)d_in[1];
    if (n_in >= 2 && in_sizes[0] > in_sizes[1]) {
        const float* tmp = patch; patch = lib; lib = tmp;
    }
    float* out = (float*)d_out;

    cudaFuncSetAttribute(gemm_bf16, cudaFuncAttributeMaxDynamicSharedMemorySize, SMEM_DYN);

    prep_kernel<<<NPAD, 128>>>(patch);
    convert_kernel<<<MPAD / 8, 256>>>(lib);
    gk_kernel<<<1, 64>>>();
    gemm_bf16<<<dim3(NPT, NTILES), 256, SMEM_DYN>>>();
    reduce1_kernel<<<NPT, 256>>>();
    argmax_kernel<<<1, 704>>>();
    argmin_kernel<<<M / 8, 256>>>();
    dstar_kernel<<<M / 8, 256>>>();
    top5_kernel<<<1, 256>>>();
    scalar_kernel<<<1, 192>>>(lib, out);
    resize_kernel<<<196, 256>>>();
    blurv_kernel<<<196, 256>>>();
    blurh_kernel<<<196, 256>>>(out);
}

// round 5
// speedup vs baseline: 4.2192x; 1.3224x over previous
#include <cuda_runtime.h>
#include <cuda_bf16.h>
#include <math.h>
#include <stdint.h>

#define N_PATCH 676
#define NPAD    768
#define NPT     6          // patch tiles of 128
#define D       384
#define M       200000
#define NTILES  1563       // lib tiles of 128
#define MPAD    (NTILES * 128)
#define NKB     6          // k-blocks of 64
#define IMG     224
#define KS      33
#define RAD     16
#define T5B     250        // dstar_top5 blocks

typedef unsigned long long ull;

__device__ __align__(128) __nv_bfloat16 g_libh[(size_t)MPAD * D];
__device__ __align__(16)  __nv_bfloat16 g_patchh[NPAD * D];
__device__ float g_patchN[NPAD * D];
__device__ float g_pn[NPAD];
__device__ float g_ln[MPAD];
__device__ ull   g_pk[(size_t)NTILES * NPAD];   // per (tile, patch-col) min key
__device__ float g_minval[N_PATCH];
__device__ int   g_minidx[N_PATCH];
__device__ float g_rmap[IMG * IMG];
__device__ float g_tmap[IMG * IMG];
__device__ float g_kern[KS];
__device__ int   g_sidx;
__device__ int   g_mstar;
__device__ float g_sstar;
__device__ ull   g_part[T5B * 5];
__device__ int   g_nn[5];

__device__ __forceinline__ uint32_t smem_u32(const void* p) {
    uint32_t a;
    asm("{ .reg .u64 t; cvta.to.shared.u64 t, %1; cvt.u32.u64 %0, t; }" : "=r"(a) : "l"(p));
    return a;
}
#define SW128(x) ((x) ^ (((x) >> 3) & 0x70))

#define CP16(dst, src) asm volatile("cp.async.cg.shared.global [%0], [%1], 16;" :: "r"(dst), "l"(src) : "memory")
#define CP_COMMIT()    asm volatile("cp.async.commit_group;" ::: "memory")
#define CP_WAIT1()     asm volatile("cp.async.wait_group 1;" ::: "memory")
#define CP_WAIT0()     asm volatile("cp.async.wait_group 0;" ::: "memory")

#define LDSM4(r0, r1, r2, r3, addr) \
    asm volatile("ldmatrix.sync.aligned.m8n8.x4.shared.b16 {%0,%1,%2,%3}, [%4];" \
        : "=r"(r0), "=r"(r1), "=r"(r2), "=r"(r3) : "r"(addr))

#define MMA16816(c, a, b0, b1) \
    asm volatile("mma.sync.aligned.m16n8k16.row.col.f32.bf16.bf16.f32 " \
        "{%0,%1,%2,%3}, {%4,%5,%6,%7}, {%8,%9}, {%0,%1,%2,%3};" \
        : "+f"((c)[0]), "+f"((c)[1]), "+f"((c)[2]), "+f"((c)[3]) \
        : "r"((a)[0]), "r"((a)[1]), "r"((a)[2]), "r"((a)[3]), "r"(b0), "r"(b1))

__device__ __forceinline__ unsigned f2ord(float v) {
    unsigned u = __float_as_uint(v);
    return (u & 0x80000000u) ? ~u : (u | 0x80000000u);
}
__device__ __forceinline__ float ord2f(unsigned o) {
    unsigned u = (o & 0x80000000u) ? (o & 0x7fffffffu) : ~o;
    return __uint_as_float(u);
}

__device__ __forceinline__ float dot8(uint4 a, uint4 b) {
    const unsigned* pa = (const unsigned*)&a;
    const unsigned* pb = (const unsigned*)&b;
    float s = 0.f;
#pragma unroll
    for (int i = 0; i < 4; i++) {
        float2 fa = __bfloat1622float2(*(const __nv_bfloat162*)&pa[i]);
        float2 fb = __bfloat1622float2(*(const __nv_bfloat162*)&pb[i]);
        s += fa.x * fb.x + fa.y * fb.y;
    }
    return s;
}

// ---------------- 1) normalize patch -> fp32 + bf16, pn ----------------
__global__ void prep_kernel(const float* __restrict__ patch) {
    int n = blockIdx.x, t = threadIdx.x;   // 128 threads
    __shared__ float red[4];
    __shared__ float bcast;
    if (n >= N_PATCH) {
        for (int c = t; c < D; c += 128) {
            g_patchN[(size_t)n * D + c] = 0.f;
            g_patchh[(size_t)n * D + c] = __float2bfloat16(0.f);
        }
        if (t == 0) g_pn[n] = 0.f;
        return;
    }
    float x0 = patch[(size_t)n * D + t];
    float x1 = patch[(size_t)n * D + t + 128];
    float x2 = patch[(size_t)n * D + t + 256];
    float s = x0 * x0 + x1 * x1 + x2 * x2;
    for (int o = 16; o > 0; o >>= 1) s += __shfl_down_sync(0xffffffffu, s, o);
    if ((t & 31) == 0) red[t >> 5] = s;
    __syncthreads();
    if (t == 0) bcast = red[0] + red[1] + red[2] + red[3];
    __syncthreads();
    float inv = 1.f / fmaxf(sqrtf(bcast), 1e-12f);
    float y0 = x0 * inv, y1 = x1 * inv, y2 = x2 * inv;
    g_patchN[(size_t)n * D + t]       = y0;
    g_patchN[(size_t)n * D + t + 128] = y1;
    g_patchN[(size_t)n * D + t + 256] = y2;
    g_patchh[(size_t)n * D + t]       = __float2bfloat16(y0);
    g_patchh[(size_t)n * D + t + 128] = __float2bfloat16(y1);
    g_patchh[(size_t)n * D + t + 256] = __float2bfloat16(y2);
    float p = y0 * y0 + y1 * y1 + y2 * y2;
    for (int o = 16; o > 0; o >>= 1) p += __shfl_down_sync(0xffffffffu, p, o);
    if ((t & 31) == 0) red[t >> 5] = p;
    __syncthreads();
    if (t == 0) g_pn[n] = red[0] + red[1] + red[2] + red[3];
}

// ---------------- 2) lib fp32 -> bf16 + row norms ----------------
__global__ void convert_kernel(const float* __restrict__ lib) {
    int t = threadIdx.x, warp = t >> 5, lane = t & 31;
    long r = (long)blockIdx.x * 8 + warp;
    if (r >= MPAD) return;
    uint2* dst = (uint2*)(g_libh + (size_t)r * D);
    if (r >= M) {
        uint2 z = make_uint2(0u, 0u);
        for (int c = lane; c < 96; c += 32) dst[c] = z;
        if (lane == 0) g_ln[r] = 1e30f;
        return;
    }
    const float4* row = (const float4*)(lib + (size_t)r * D);
    float s = 0.f;
#pragma unroll
    for (int j = 0; j < 3; j++) {
        float4 v = row[lane + 32 * j];
        s += v.x * v.x + v.y * v.y + v.z * v.z + v.w * v.w;
        __nv_bfloat162 p0 = __float22bfloat162_rn(make_float2(v.x, v.y));
        __nv_bfloat162 p1 = __float22bfloat162_rn(make_float2(v.z, v.w));
        uint2 o;
        o.x = *reinterpret_cast<unsigned*>(&p0);
        o.y = *reinterpret_cast<unsigned*>(&p1);
        dst[lane + 32 * j] = o;
    }
    for (int o = 16; o > 0; o >>= 1) s += __shfl_down_sync(0xffffffffu, s, o);
    if (lane == 0) g_ln[r] = s;
}

// ---------------- 3) gaussian kernel ----------------
__global__ void gk_kernel() {
    __shared__ float w[KS];
    int t = threadIdx.x;
    if (t < KS) {
        float x = (float)(t - RAD);
        w[t] = expf(-0.5f * (x / 4.f) * (x / 4.f));
    }
    __syncthreads();
    if (t == 0) {
        float s = 0.f;
        for (int i = 0; i < KS; i++) s += w[i];
        for (int i = 0; i < KS; i++) g_kern[i] = w[i] / s;
    }
}

// ---------------- 4) bf16 HMMA GEMM, 3-stage pipeline, key epilogue ----------------
// stage s: A @ s*32768 (16KB), B @ s*32768+16384 (16KB). 3 stages = 96KB.
#define SMEM_DYN 98304

__global__ void __launch_bounds__(256, 2) gemm_bf16() {
    extern __shared__ char dyn[];
    __shared__ float ln_s[128];
    __shared__ ull scmb[2][128];

    int t = threadIdx.x;
    int pt = blockIdx.x;       // patch tile (fast -> lib tile L2 reuse)
    int tile = blockIdx.y;     // lib tile
    int lane = t & 31, warp = t >> 5;
    int wm = warp >> 2, wn = warp & 3;

    uint32_t sbase = smem_u32(dyn);
    const char* gA = (const char*)g_libh + (size_t)tile * 128 * 768;
    const char* gB = (const char*)g_patchh + (size_t)pt * 128 * 768;

    if (t < 128) ln_s[t] = g_ln[(size_t)tile * 128 + t];

    int id_row = t >> 3, id_seg = t & 7;   // per-thread fixed roles (32 rows per i-step)
    // issue stage kb -> slot kb%3
#define ISSUE(kb) do { \
        int slot_ = (kb) % 3; \
        const char* ga_ = gA + (kb) * 128; \
        const char* gb_ = gB + (kb) * 128; \
        _Pragma("unroll") \
        for (int i_ = 0; i_ < 4; i_++) { \
            int row_ = i_ * 32 + id_row; \
            uint32_t off_ = SW128((uint32_t)(row_ * 128 + id_seg * 16)); \
            CP16(sbase + slot_ * 32768 + off_, ga_ + (size_t)row_ * 768 + id_seg * 16); \
            CP16(sbase + slot_ * 32768 + 16384 + off_, gb_ + (size_t)row_ * 768 + id_seg * 16); \
        } \
        CP_COMMIT(); \
    } while (0)

    ISSUE(0);
    ISSUE(1);

    float c[4][4][4];
#pragma unroll
    for (int mi = 0; mi < 4; mi++)
#pragma unroll
        for (int ni = 0; ni < 4; ni++)
#pragma unroll
            for (int k = 0; k < 4; k++) c[mi][ni][k] = 0.f;

#pragma unroll
    for (int kb = 0; kb < NKB; kb++) {
        if (kb < NKB - 1) CP_WAIT1(); else CP_WAIT0();
        __syncthreads();
        if (kb + 2 < NKB) ISSUE(kb + 2);
        int slot = kb % 3;
        uint32_t sA = sbase + slot * 32768;
        uint32_t sB = sA + 16384;
#pragma unroll
        for (int ks = 0; ks < 4; ks++) {
            uint32_t a[4][4];
#pragma unroll
            for (int mi = 0; mi < 4; mi++) {
                uint32_t byte = (uint32_t)((wm * 64 + mi * 16 + (lane & 15)) * 128
                                           + ks * 32 + (lane >> 4) * 16);
                LDSM4(a[mi][0], a[mi][1], a[mi][2], a[mi][3], sA + SW128(byte));
            }
            uint32_t b[4][2];
#pragma unroll
            for (int nh = 0; nh < 2; nh++) {
                uint32_t byte = (uint32_t)((wn * 32 + nh * 16 + (lane & 15)) * 128
                                           + ks * 32 + (lane >> 4) * 16);
                uint32_t r0, r1, r2, r3;
                LDSM4(r0, r1, r2, r3, sB + SW128(byte));
                b[nh * 2][0] = r0; b[nh * 2 + 1][0] = r1;
                b[nh * 2][1] = r2; b[nh * 2 + 1][1] = r3;
            }
#pragma unroll
            for (int mi = 0; mi < 4; mi++)
#pragma unroll
                for (int ni = 0; ni < 4; ni++)
                    MMA16816(c[mi][ni], a[mi], b[ni][0], b[ni][1]);
        }
        // no trailing sync: next iter's top sync protects slot reuse
    }

    // epilogue: key = (f2ord(ln - 2 dot) << 32) | lib_row ; min over 128 rows per col
    unsigned rbase = (unsigned)tile * 128u + (unsigned)(wm * 64) + (unsigned)(lane >> 2);
#pragma unroll
    for (int ni = 0; ni < 4; ni++) {
        ull k0 = ~0ull, k1 = ~0ull;
#pragma unroll
        for (int mi = 0; mi < 4; mi++) {
            int rloc = wm * 64 + mi * 16 + (lane >> 2);
            float l0 = ln_s[rloc], l1 = ln_s[rloc + 8];
            unsigned r0 = rbase + mi * 16, r1 = r0 + 8;
            float v; ull k;
            v = fmaf(-2.f, c[mi][ni][0], l0); k = ((ull)f2ord(v) << 32) | r0; k0 = min(k0, k);
            v = fmaf(-2.f, c[mi][ni][2], l1); k = ((ull)f2ord(v) << 32) | r1; k0 = min(k0, k);
            v = fmaf(-2.f, c[mi][ni][1], l0); k = ((ull)f2ord(v) << 32) | r0; k1 = min(k1, k);
            v = fmaf(-2.f, c[mi][ni][3], l1); k = ((ull)f2ord(v) << 32) | r1; k1 = min(k1, k);
        }
#pragma unroll
        for (int off = 4; off < 32; off <<= 1) {
            k0 = min(k0, __shfl_xor_sync(0xffffffffu, k0, off));
            k1 = min(k1, __shfl_xor_sync(0xffffffffu, k1, off));
        }
        if (lane < 4) {
            scmb[wm][wn * 32 + ni * 8 + lane * 2 + 0] = k0;
            scmb[wm][wn * 32 + ni * 8 + lane * 2 + 1] = k1;
        }
    }
    __syncthreads();
    if (t < 128)
        g_pk[(size_t)tile * NPAD + pt * 128 + t] = min(scmb[0][t], scmb[1][t]);
}

// ---------------- 5) per-col min over lib tiles -> minval + minidx ----------------
__global__ void reduce1_kernel() {
    int pt = blockIdx.x, t = threadIdx.x;  // 6 blocks x 256
    int col = t & 127, half = t >> 7;
    ull m = ~0ull;
    for (int tile = half; tile < NTILES; tile += 2)
        m = min(m, g_pk[(size_t)tile * NPAD + pt * 128 + col]);
    __shared__ ull sm[256];
    sm[t] = m;
    __syncthreads();
    if (t < 128) {
        int n = pt * 128 + col;
        if (n < N_PATCH) {
            ull k = min(sm[t], sm[t + 128]);
            float v = ord2f((unsigned)(k >> 32));
            g_minval[n] = sqrtf(fmaxf(g_pn[n] + v, 0.f));
            g_minidx[n] = (int)(k & 0xffffffffu);
        }
    }
}

// ---------------- 6) argmax over patch rows ----------------
__global__ void argmax_kernel() {
    int t = threadIdx.x;  // 704
    __shared__ float sv[704];
    __shared__ int si[704];
    float val = (t < N_PATCH) ? g_minval[t] : -3.4e38f;
    sv[t] = val; si[t] = t;
    __syncthreads();
    for (int s = 512; s > 0; s >>= 1) {
        if (t < s && t + s < 704) {
            if (sv[t + s] > sv[t] || (sv[t + s] == sv[t] && si[t + s] < si[t])) {
                sv[t] = sv[t + s]; si[t] = si[t + s];
            }
        }
        __syncthreads();
    }
    if (t == 0) {
        g_sidx = si[0];
        g_sstar = sv[0];
        g_mstar = g_minidx[si[0]];
    }
}

// ---------------- 7) fused d_star + per-block top5 ----------------
__global__ void dstar_top5() {
    __shared__ uint4 q[48];
    __shared__ float smsn;
    __shared__ int sms;
    __shared__ ull wk[8][5];
    int t = threadIdx.x, warp = t >> 5, lane = t & 31;
    if (t == 0) sms = g_mstar;
    __syncthreads();
    if (t < 48) q[t] = ((const uint4*)(g_libh + (size_t)sms * D))[t];
    if (t == 63) smsn = g_ln[sms];
    __syncthreads();
    ull top[5];
#pragma unroll
    for (int k = 0; k < 5; k++) top[k] = ~0ull;
    for (int it = 0; it < 100; it++) {
        long r = (long)blockIdx.x * 800 + it * 8 + warp;
        const uint4* row = (const uint4*)(g_libh + (size_t)r * D);
        float s = dot8(row[lane], q[lane]);
        if (lane < 16) s += dot8(row[32 + lane], q[32 + lane]);
        for (int o = 16; o > 0; o >>= 1) s += __shfl_down_sync(0xffffffffu, s, o);
        if (lane == 0) {
            float d2 = g_ln[r] + smsn - 2.f * s;
            ull key = ((ull)f2ord(d2) << 32) | (unsigned)r;
            if (key < top[4]) {
                top[4] = key;
#pragma unroll
                for (int k = 4; k > 0; k--)
                    if (top[k] < top[k - 1]) { ull tv = top[k]; top[k] = top[k - 1]; top[k - 1] = tv; }
            }
        }
    }
    if (lane == 0)
#pragma unroll
        for (int k = 0; k < 5; k++) wk[warp][k] = top[k];
    __syncthreads();
    if (t == 0) {
        ull last = 0;
        for (int sel = 0; sel < 5; sel++) {
            ull best = ~0ull;
            for (int i = 0; i < 40; i++) {
                ull k = wk[i / 5][i % 5];
                if (k > last && k < best) best = k;
            }
            g_part[blockIdx.x * 5 + sel] = best;
            last = best;
        }
    }
}

// ---------------- 8) merge per-block top5 -> global top5 ----------------
__global__ void top5m_kernel() {
    __shared__ ull keys[T5B * 5];
    __shared__ ull red[256];
    int t = threadIdx.x;
    for (int i = t; i < T5B * 5; i += 256) keys[i] = g_part[i];
    __syncthreads();
    ull last = 0;
    for (int sel = 0; sel < 5; sel++) {
        ull best = ~0ull;
        for (int i = t; i < T5B * 5; i += 256) {
            ull k = keys[i];
            if (k > last && k < best) best = k;
        }
        red[t] = best;
        __syncthreads();
        for (int s = 128; s > 0; s >>= 1) {
            if (t < s) red[t] = min(red[t], red[t + s]);
            __syncthreads();
        }
        if (t == 0) g_nn[sel] = (int)(red[0] & 0xffffffffu);
        last = red[0];
        __syncthreads();
    }
}

// ---------------- 9) scalar s (fp32) ----------------
__global__ void scalar_kernel(const float* __restrict__ lib, float* __restrict__ out) {
    __shared__ float dd[6];
    __shared__ int tgt[6];
    int t = threadIdx.x, warp = t >> 5, lane = t & 31;  // 192 threads
    if (t < 5) tgt[t] = g_nn[t];
    if (t == 5) tgt[5] = g_mstar;
    __syncthreads();
    {
        long rm = tgt[warp];
        const float* p = g_patchN + (size_t)g_sidx * D;
        const float* q = lib + (size_t)rm * D;
        float s = 0.f;
        for (int c = lane; c < D; c += 32) {
            float d = p[c] - q[c];
            s += d * d;
        }
        for (int o = 16; o > 0; o >>= 1) s += __shfl_down_sync(0xffffffffu, s, o);
        if (lane == 0) dd[warp] = sqrtf(s);
    }
    __syncthreads();
    if (t == 0) {
        float den = 0.f;
        for (int k = 0; k < 5; k++) den += expf(dd[k]);
        float num = expf(dd[5]);
        out[0] = (1.f - num / den) * g_sstar;
    }
}

// ---------------- 10) bilinear 26->224 ----------------
__global__ void resize_kernel() {
    int idx = blockIdx.x * 256 + threadIdx.x;
    if (idx >= IMG * IMG) return;
    int y = idx / IMG, x = idx % IMG;
    const float scale = 26.f / 224.f;
    float fy = (y + 0.5f) * scale - 0.5f;
    float fx = (x + 0.5f) * scale - 0.5f;
    int y0 = (int)floorf(fy), x0 = (int)floorf(fx);
    float wy = fy - (float)y0, wx = fx - (float)x0;
    int y0c = min(max(y0, 0), 25), y1c = min(max(y0 + 1, 0), 25);
    int x0c = min(max(x0, 0), 25), x1c = min(max(x0 + 1, 0), 25);
    float v00 = g_minval[y0c * 26 + x0c], v01 = g_minval[y0c * 26 + x1c];
    float v10 = g_minval[y1c * 26 + x0c], v11 = g_minval[y1c * 26 + x1c];
    g_rmap[idx] = (1.f - wy) * ((1.f - wx) * v00 + wx * v01)
                + wy * ((1.f - wx) * v10 + wx * v11);
}

__device__ __forceinline__ int reflect_idx(int i) {
    if (i < 0) return -i;
    if (i > IMG - 1) return 2 * (IMG - 1) - i;
    return i;
}

__global__ void blurv_kernel() {
    __shared__ float kw[KS];
    int t = threadIdx.x;
    if (t < KS) kw[t] = g_kern[t];
    __syncthreads();
    int idx = blockIdx.x * 256 + t;
    if (idx >= IMG * IMG) return;
    int y = idx / IMG, x = idx % IMG;
    float s = 0.f;
#pragma unroll
    for (int d = 0; d < KS; d++)
        s += kw[d] * g_rmap[reflect_idx(y + d - RAD) * IMG + x];
    g_tmap[idx] = s;
}

__global__ void blurh_kernel(float* __restrict__ out) {
    __shared__ float kw[KS];
    int t = threadIdx.x;
    if (t < KS) kw[t] = g_kern[t];
    __syncthreads();
    int idx = blockIdx.x * 256 + t;
    if (idx >= IMG * IMG) return;
    int y = idx / IMG, x = idx % IMG;
    float s = 0.f;
#pragma unroll
    for (int d = 0; d < KS; d++)
        s += kw[d] * g_tmap[y * IMG + reflect_idx(x + d - RAD)];
    out[1 + idx] = s;
}

// ---------------- launch ----------------
extern "C" void kernel_launch(void* const* d_in, const int* in_sizes, int n_in,
                              void* d_out, int out_size) {
    const float* patch = (const float*)d_in[0];
    const float* lib   = (const float*)d_in[1];
    if (n_in >= 2 && in_sizes[0] > in_sizes[1]) {
        const float* tmp = patch; patch = lib; lib = tmp;
    }
    float* out = (float*)d_out;

    cudaFuncSetAttribute(gemm_bf16, cudaFuncAttributeMaxDynamicSharedMemorySize, SMEM_DYN);

    prep_kernel<<<NPAD, 128>>>(patch);
    convert_kernel<<<MPAD / 8, 256>>>(lib);
    gk_kernel<<<1, 64>>>();
    gemm_bf16<<<dim3(NPT, NTILES), 256, SMEM_DYN>>>();
    reduce1_kernel<<<NPT, 256>>>();
    argmax_kernel<<<1, 704>>>();
    dstar_top5<<<T5B, 256>>>();
    top5m_kernel<<<1, 256>>>();
    scalar_kernel<<<1, 192>>>(lib, out);
    resize_kernel<<<196, 256>>>();
    blurv_kernel<<<196, 256>>>();
    blurh_kernel<<<196, 256>>>(out);
}

// round 6
// speedup vs baseline: 4.2292x; 1.0024x over previous
#include <cuda_runtime.h>
#include <cuda_bf16.h>
#include <math.h>
#include <stdint.h>

#define N_PATCH 676
#define NPAD    768
#define NPT     6          // patch tiles of 128
#define D       384
#define M       200000
#define NTILES  1563       // lib tiles of 128
#define MPAD    (NTILES * 128)
#define NKB     6          // k-blocks of 64
#define IMG     224
#define KS      33
#define RAD     16
#define T5B     250        // dstar_top5 blocks

typedef unsigned long long ull;

__device__ __align__(128) __nv_bfloat16 g_libh[(size_t)MPAD * D];
__device__ __align__(16)  __nv_bfloat16 g_patchh[NPAD * D];
__device__ float g_patchN[NPAD * D];
__device__ float g_pn[NPAD];
__device__ float g_ln[MPAD];
__device__ ull   g_pk[(size_t)NTILES * NPAD];   // per (tile, patch-col) min key
__device__ float g_minval[N_PATCH];
__device__ int   g_minidx[N_PATCH];
__device__ float g_rmap[IMG * IMG];
__device__ float g_tmap[IMG * IMG];
__device__ int   g_sidx;
__device__ int   g_mstar;
__device__ float g_sstar;
__device__ ull   g_part[T5B * 5];
__device__ int   g_nn[5];

__device__ __forceinline__ uint32_t smem_u32(const void* p) {
    uint32_t a;
    asm("{ .reg .u64 t; cvta.to.shared.u64 t, %1; cvt.u32.u64 %0, t; }" : "=r"(a) : "l"(p));
    return a;
}
#define SW128(x) ((x) ^ (((x) >> 3) & 0x70))

#define CP16(dst, src) asm volatile("cp.async.cg.shared.global [%0], [%1], 16;" :: "r"(dst), "l"(src) : "memory")
#define CP_COMMIT()    asm volatile("cp.async.commit_group;" ::: "memory")
#define CP_WAIT1()     asm volatile("cp.async.wait_group 1;" ::: "memory")
#define CP_WAIT0()     asm volatile("cp.async.wait_group 0;" ::: "memory")

#define LDSM4(r0, r1, r2, r3, addr) \
    asm volatile("ldmatrix.sync.aligned.m8n8.x4.shared.b16 {%0,%1,%2,%3}, [%4];" \
        : "=r"(r0), "=r"(r1), "=r"(r2), "=r"(r3) : "r"(addr))

#define MMA16816(c, a, b0, b1) \
    asm volatile("mma.sync.aligned.m16n8k16.row.col.f32.bf16.bf16.f32 " \
        "{%0,%1,%2,%3}, {%4,%5,%6,%7}, {%8,%9}, {%0,%1,%2,%3};" \
        : "+f"((c)[0]), "+f"((c)[1]), "+f"((c)[2]), "+f"((c)[3]) \
        : "r"((a)[0]), "r"((a)[1]), "r"((a)[2]), "r"((a)[3]), "r"(b0), "r"(b1))

__device__ __forceinline__ unsigned f2ord(float v) {
    unsigned u = __float_as_uint(v);
    return (u & 0x80000000u) ? ~u : (u | 0x80000000u);
}
__device__ __forceinline__ float ord2f(unsigned o) {
    unsigned u = (o & 0x80000000u) ? (o & 0x7fffffffu) : ~o;
    return __uint_as_float(u);
}

__device__ __forceinline__ float dot8(uint4 a, uint4 b) {
    const unsigned* pa = (const unsigned*)&a;
    const unsigned* pb = (const unsigned*)&b;
    float s = 0.f;
#pragma unroll
    for (int i = 0; i < 4; i++) {
        float2 fa = __bfloat1622float2(*(const __nv_bfloat162*)&pa[i]);
        float2 fb = __bfloat1622float2(*(const __nv_bfloat162*)&pb[i]);
        s += fa.x * fb.x + fa.y * fb.y;
    }
    return s;
}

// ---------------- 1) normalize patch -> fp32 + bf16, pn ----------------
__global__ void prep_kernel(const float* __restrict__ patch) {
    int n = blockIdx.x, t = threadIdx.x;   // 128 threads
    __shared__ float red[4];
    __shared__ float bcast;
    if (n >= N_PATCH) {
        for (int c = t; c < D; c += 128) {
            g_patchN[(size_t)n * D + c] = 0.f;
            g_patchh[(size_t)n * D + c] = __float2bfloat16(0.f);
        }
        if (t == 0) g_pn[n] = 0.f;
        return;
    }
    float x0 = patch[(size_t)n * D + t];
    float x1 = patch[(size_t)n * D + t + 128];
    float x2 = patch[(size_t)n * D + t + 256];
    float s = x0 * x0 + x1 * x1 + x2 * x2;
    for (int o = 16; o > 0; o >>= 1) s += __shfl_down_sync(0xffffffffu, s, o);
    if ((t & 31) == 0) red[t >> 5] = s;
    __syncthreads();
    if (t == 0) bcast = red[0] + red[1] + red[2] + red[3];
    __syncthreads();
    float inv = 1.f / fmaxf(sqrtf(bcast), 1e-12f);
    float y0 = x0 * inv, y1 = x1 * inv, y2 = x2 * inv;
    g_patchN[(size_t)n * D + t]       = y0;
    g_patchN[(size_t)n * D + t + 128] = y1;
    g_patchN[(size_t)n * D + t + 256] = y2;
    g_patchh[(size_t)n * D + t]       = __float2bfloat16(y0);
    g_patchh[(size_t)n * D + t + 128] = __float2bfloat16(y1);
    g_patchh[(size_t)n * D + t + 256] = __float2bfloat16(y2);
    float p = y0 * y0 + y1 * y1 + y2 * y2;
    for (int o = 16; o > 0; o >>= 1) p += __shfl_down_sync(0xffffffffu, p, o);
    if ((t & 31) == 0) red[t >> 5] = p;
    __syncthreads();
    if (t == 0) g_pn[n] = red[0] + red[1] + red[2] + red[3];
}

// ---------------- 2) lib fp32 -> bf16 + row norms ----------------
__global__ void convert_kernel(const float* __restrict__ lib) {
    int t = threadIdx.x, warp = t >> 5, lane = t & 31;
    long r = (long)blockIdx.x * 8 + warp;
    if (r >= MPAD) return;
    uint2* dst = (uint2*)(g_libh + (size_t)r * D);
    if (r >= M) {
        uint2 z = make_uint2(0u, 0u);
        for (int c = lane; c < 96; c += 32) dst[c] = z;
        if (lane == 0) g_ln[r] = 1e30f;
        return;
    }
    const float4* row = (const float4*)(lib + (size_t)r * D);
    float s = 0.f;
#pragma unroll
    for (int j = 0; j < 3; j++) {
        float4 v = row[lane + 32 * j];
        s += v.x * v.x + v.y * v.y + v.z * v.z + v.w * v.w;
        __nv_bfloat162 p0 = __float22bfloat162_rn(make_float2(v.x, v.y));
        __nv_bfloat162 p1 = __float22bfloat162_rn(make_float2(v.z, v.w));
        uint2 o;
        o.x = *reinterpret_cast<unsigned*>(&p0);
        o.y = *reinterpret_cast<unsigned*>(&p1);
        dst[lane + 32 * j] = o;
    }
    for (int o = 16; o > 0; o >>= 1) s += __shfl_down_sync(0xffffffffu, s, o);
    if (lane == 0) g_ln[r] = s;
}

// ---------------- 3) bf16 HMMA GEMM, 2-stage pipeline, key epilogue ----------------
// As[2] @ 0/16384 (16KB each), Bs[2] @ 32768/49152. Total 64KB dyn smem.
#define SMEM_DYN 65536

__global__ void __launch_bounds__(256, 2) gemm_bf16() {
    extern __shared__ char dyn[];
    __shared__ float ln_s[128];
    __shared__ ull scmb[2][128];

    int t = threadIdx.x;
    int pt = blockIdx.x;       // patch tile (fast -> lib tile L2 reuse)
    int tile = blockIdx.y;     // lib tile
    int lane = t & 31, warp = t >> 5;
    int wm = warp >> 2, wn = warp & 3;

    uint32_t sbase = smem_u32(dyn);
    const char* gA = (const char*)g_libh + (size_t)tile * 128 * 768;
    const char* gB = (const char*)g_patchh + (size_t)pt * 128 * 768;

    if (t < 128) ln_s[t] = g_ln[(size_t)tile * 128 + t];

    // preload k-block 0
#pragma unroll
    for (int i = 0; i < 4; i++) {
        int id = i * 256 + t; int row = id >> 3, seg = id & 7;
        uint32_t off = SW128((uint32_t)(row * 128 + seg * 16));
        CP16(sbase + off, gA + (size_t)row * 768 + seg * 16);
        CP16(sbase + 32768 + off, gB + (size_t)row * 768 + seg * 16);
    }
    CP_COMMIT();

    float c[4][4][4];
#pragma unroll
    for (int mi = 0; mi < 4; mi++)
#pragma unroll
        for (int ni = 0; ni < 4; ni++)
#pragma unroll
            for (int k = 0; k < 4; k++) c[mi][ni][k] = 0.f;

    for (int kb = 0; kb < NKB; kb++) {
        int buf = kb & 1;
        if (kb < NKB - 1) {
            int nb = buf ^ 1;
            const char* ga = gA + (kb + 1) * 128;
            const char* gb = gB + (kb + 1) * 128;
#pragma unroll
            for (int i = 0; i < 4; i++) {
                int id = i * 256 + t; int row = id >> 3, seg = id & 7;
                uint32_t off = SW128((uint32_t)(row * 128 + seg * 16));
                CP16(sbase + nb * 16384 + off, ga + (size_t)row * 768 + seg * 16);
                CP16(sbase + 32768 + nb * 16384 + off, gb + (size_t)row * 768 + seg * 16);
            }
            CP_COMMIT();
            CP_WAIT1();
        } else {
            CP_WAIT0();
        }
        __syncthreads();
        uint32_t sA = sbase + buf * 16384;
        uint32_t sB = sbase + 32768 + buf * 16384;
#pragma unroll
        for (int ks = 0; ks < 4; ks++) {
            uint32_t a[4][4];
#pragma unroll
            for (int mi = 0; mi < 4; mi++) {
                uint32_t byte = (uint32_t)((wm * 64 + mi * 16 + (lane & 15)) * 128
                                           + ks * 32 + (lane >> 4) * 16);
                LDSM4(a[mi][0], a[mi][1], a[mi][2], a[mi][3], sA + SW128(byte));
            }
            uint32_t b[4][2];
#pragma unroll
            for (int nh = 0; nh < 2; nh++) {
                uint32_t byte = (uint32_t)((wn * 32 + nh * 16 + (lane & 15)) * 128
                                           + ks * 32 + (lane >> 4) * 16);
                uint32_t r0, r1, r2, r3;
                LDSM4(r0, r1, r2, r3, sB + SW128(byte));
                b[nh * 2][0] = r0; b[nh * 2 + 1][0] = r1;
                b[nh * 2][1] = r2; b[nh * 2 + 1][1] = r3;
            }
#pragma unroll
            for (int mi = 0; mi < 4; mi++)
#pragma unroll
                for (int ni = 0; ni < 4; ni++)
                    MMA16816(c[mi][ni], a[mi], b[ni][0], b[ni][1]);
        }
        __syncthreads();
    }

    // epilogue: key = (f2ord(ln - 2 dot) << 32) | lib_row ; min over 128 rows per col
    unsigned rbase = (unsigned)tile * 128u + (unsigned)(wm * 64) + (unsigned)(lane >> 2);
#pragma unroll
    for (int ni = 0; ni < 4; ni++) {
        ull k0 = ~0ull, k1 = ~0ull;
#pragma unroll
        for (int mi = 0; mi < 4; mi++) {
            int rloc = wm * 64 + mi * 16 + (lane >> 2);
            float l0 = ln_s[rloc], l1 = ln_s[rloc + 8];
            unsigned r0 = rbase + mi * 16, r1 = r0 + 8;
            float v; ull k;
            v = fmaf(-2.f, c[mi][ni][0], l0); k = ((ull)f2ord(v) << 32) | r0; k0 = min(k0, k);
            v = fmaf(-2.f, c[mi][ni][2], l1); k = ((ull)f2ord(v) << 32) | r1; k0 = min(k0, k);
            v = fmaf(-2.f, c[mi][ni][1], l0); k = ((ull)f2ord(v) << 32) | r0; k1 = min(k1, k);
            v = fmaf(-2.f, c[mi][ni][3], l1); k = ((ull)f2ord(v) << 32) | r1; k1 = min(k1, k);
        }
#pragma unroll
        for (int off = 4; off < 32; off <<= 1) {
            k0 = min(k0, __shfl_xor_sync(0xffffffffu, k0, off));
            k1 = min(k1, __shfl_xor_sync(0xffffffffu, k1, off));
        }
        if (lane < 4) {
            scmb[wm][wn * 32 + ni * 8 + lane * 2 + 0] = k0;
            scmb[wm][wn * 32 + ni * 8 + lane * 2 + 1] = k1;
        }
    }
    __syncthreads();
    if (t < 128)
        g_pk[(size_t)tile * NPAD + pt * 128 + t] = min(scmb[0][t], scmb[1][t]);
}

// ---------------- 4) per-col min over lib tiles -> minval + minidx ----------------
__global__ void reduce1_kernel() {
    int pt = blockIdx.x, t = threadIdx.x;  // 6 blocks x 256
    int col = t & 127, half = t >> 7;
    ull m = ~0ull;
    for (int tile = half; tile < NTILES; tile += 2)
        m = min(m, g_pk[(size_t)tile * NPAD + pt * 128 + col]);
    __shared__ ull sm[256];
    sm[t] = m;
    __syncthreads();
    if (t < 128) {
        int n = pt * 128 + col;
        if (n < N_PATCH) {
            ull k = min(sm[t], sm[t + 128]);
            float v = ord2f((unsigned)(k >> 32));
            g_minval[n] = sqrtf(fmaxf(g_pn[n] + v, 0.f));
            g_minidx[n] = (int)(k & 0xffffffffu);
        }
    }
}

// ---------------- 5) argmax over patch rows ----------------
__global__ void argmax_kernel() {
    int t = threadIdx.x;  // 704
    __shared__ float sv[704];
    __shared__ int si[704];
    float val = (t < N_PATCH) ? g_minval[t] : -3.4e38f;
    sv[t] = val; si[t] = t;
    __syncthreads();
    for (int s = 512; s > 0; s >>= 1) {
        if (t < s && t + s < 704) {
            if (sv[t + s] > sv[t] || (sv[t + s] == sv[t] && si[t + s] < si[t])) {
                sv[t] = sv[t + s]; si[t] = si[t + s];
            }
        }
        __syncthreads();
    }
    if (t == 0) {
        g_sidx = si[0];
        g_sstar = sv[0];
        g_mstar = g_minidx[si[0]];
    }
}

// ---------------- 6) fused d_star + per-block top5 ----------------
__global__ void dstar_top5() {
    __shared__ uint4 q[48];
    __shared__ float smsn;
    __shared__ int sms;
    __shared__ ull wk[8][5];
    int t = threadIdx.x, warp = t >> 5, lane = t & 31;
    if (t == 0) sms = g_mstar;
    __syncthreads();
    if (t < 48) q[t] = ((const uint4*)(g_libh + (size_t)sms * D))[t];
    if (t == 63) smsn = g_ln[sms];
    __syncthreads();
    ull top[5];
#pragma unroll
    for (int k = 0; k < 5; k++) top[k] = ~0ull;
    for (int it = 0; it < 100; it++) {
        long r = (long)blockIdx.x * 800 + it * 8 + warp;
        const uint4* row = (const uint4*)(g_libh + (size_t)r * D);
        float s = dot8(row[lane], q[lane]);
        if (lane < 16) s += dot8(row[32 + lane], q[32 + lane]);
        for (int o = 16; o > 0; o >>= 1) s += __shfl_down_sync(0xffffffffu, s, o);
        if (lane == 0) {
            float d2 = g_ln[r] + smsn - 2.f * s;
            ull key = ((ull)f2ord(d2) << 32) | (unsigned)r;
            if (key < top[4]) {
                top[4] = key;
#pragma unroll
                for (int k = 4; k > 0; k--)
                    if (top[k] < top[k - 1]) { ull tv = top[k]; top[k] = top[k - 1]; top[k - 1] = tv; }
            }
        }
    }
    if (lane == 0)
#pragma unroll
        for (int k = 0; k < 5; k++) wk[warp][k] = top[k];
    __syncthreads();
    if (t == 0) {
        ull last = 0;
        for (int sel = 0; sel < 5; sel++) {
            ull best = ~0ull;
            for (int i = 0; i < 40; i++) {
                ull k = wk[i / 5][i % 5];
                if (k > last && k < best) best = k;
            }
            g_part[blockIdx.x * 5 + sel] = best;
            last = best;
        }
    }
}

// ---------------- 7) merge per-block top5 -> global top5 ----------------
__global__ void top5m_kernel() {
    __shared__ ull keys[T5B * 5];
    __shared__ ull red[256];
    int t = threadIdx.x;
    for (int i = t; i < T5B * 5; i += 256) keys[i] = g_part[i];
    __syncthreads();
    ull last = 0;
    for (int sel = 0; sel < 5; sel++) {
        ull best = ~0ull;
        for (int i = t; i < T5B * 5; i += 256) {
            ull k = keys[i];
            if (k > last && k < best) best = k;
        }
        red[t] = best;
        __syncthreads();
        for (int s = 128; s > 0; s >>= 1) {
            if (t < s) red[t] = min(red[t], red[t + s]);
            __syncthreads();
        }
        if (t == 0) g_nn[sel] = (int)(red[0] & 0xffffffffu);
        last = red[0];
        __syncthreads();
    }
}

// ---------------- 8) scalar s (fp32) ----------------
__global__ void scalar_kernel(const float* __restrict__ lib, float* __restrict__ out) {
    __shared__ float dd[6];
    __shared__ int tgt[6];
    int t = threadIdx.x, warp = t >> 5, lane = t & 31;  // 192 threads
    if (t < 5) tgt[t] = g_nn[t];
    if (t == 5) tgt[5] = g_mstar;
    __syncthreads();
    {
        long rm = tgt[warp];
        const float* p = g_patchN + (size_t)g_sidx * D;
        const float* q = lib + (size_t)rm * D;
        float s = 0.f;
        for (int c = lane; c < D; c += 32) {
            float d = p[c] - q[c];
            s += d * d;
        }
        for (int o = 16; o > 0; o >>= 1) s += __shfl_down_sync(0xffffffffu, s, o);
        if (lane == 0) dd[warp] = sqrtf(s);
    }
    __syncthreads();
    if (t == 0) {
        float den = 0.f;
        for (int k = 0; k < 5; k++) den += expf(dd[k]);
        float num = expf(dd[5]);
        out[0] = (1.f - num / den) * g_sstar;
    }
}

// ---------------- 9) bilinear 26->224 ----------------
__global__ void resize_kernel() {
    int idx = blockIdx.x * 256 + threadIdx.x;
    if (idx >= IMG * IMG) return;
    int y = idx / IMG, x = idx % IMG;
    const float scale = 26.f / 224.f;
    float fy = (y + 0.5f) * scale - 0.5f;
    float fx = (x + 0.5f) * scale - 0.5f;
    int y0 = (int)floorf(fy), x0 = (int)floorf(fx);
    float wy = fy - (float)y0, wx = fx - (float)x0;
    int y0c = min(max(y0, 0), 25), y1c = min(max(y0 + 1, 0), 25);
    int x0c = min(max(x0, 0), 25), x1c = min(max(x0 + 1, 0), 25);
    float v00 = g_minval[y0c * 26 + x0c], v01 = g_minval[y0c * 26 + x1c];
    float v10 = g_minval[y1c * 26 + x0c], v11 = g_minval[y1c * 26 + x1c];
    g_rmap[idx] = (1.f - wy) * ((1.f - wx) * v00 + wx * v01)
                + wy * ((1.f - wx) * v10 + wx * v11);
}

__device__ __forceinline__ int reflect_idx(int i) {
    if (i < 0) return -i;
    if (i > IMG - 1) return 2 * (IMG - 1) - i;
    return i;
}

// blur kernels compute unnormalized gaussian weights locally; divide sum at end
__global__ void blurv_kernel() {
    __shared__ float kw[KS];
    int t = threadIdx.x;
    if (t < KS) {
        float x = (float)(t - RAD);
        kw[t] = expf(-0.5f * (x / 4.f) * (x / 4.f));
    }
    __syncthreads();
    float wsum = 0.f;
#pragma unroll
    for (int d = 0; d < KS; d++) wsum += kw[d];
    int idx = blockIdx.x * 256 + t;
    if (idx >= IMG * IMG) return;
    int y = idx / IMG, x = idx % IMG;
    float s = 0.f;
#pragma unroll
    for (int d = 0; d < KS; d++)
        s += kw[d] * g_rmap[reflect_idx(y + d - RAD) * IMG + x];
    g_tmap[idx] = s / wsum;
}

__global__ void blurh_kernel(float* __restrict__ out) {
    __shared__ float kw[KS];
    int t = threadIdx.x;
    if (t < KS) {
        float x = (float)(t - RAD);
        kw[t] = expf(-0.5f * (x / 4.f) * (x / 4.f));
    }
    __syncthreads();
    float wsum = 0.f;
#pragma unroll
    for (int d = 0; d < KS; d++) wsum += kw[d];
    int idx = blockIdx.x * 256 + t;
    if (idx >= IMG * IMG) return;
    int y = idx / IMG, x = idx % IMG;
    float s = 0.f;
#pragma unroll
    for (int d = 0; d < KS; d++)
        s += kw[d] * g_tmap[y * IMG + reflect_idx(x + d - RAD)];
    out[1 + idx] = s / wsum;
}

// ---------------- launch ----------------
extern "C" void kernel_launch(void* const* d_in, const int* in_sizes, int n_in,
                              void* d_out, int out_size) {
    const float* patch = (const float*)d_in[0];
    const float* lib   = (const float*)d_in[1];
    if (n_in >= 2 && in_sizes[0] > in_sizes[1]) {
        const float* tmp = patch; patch = lib; lib = tmp;
    }
    float* out = (float*)d_out;

    cudaFuncSetAttribute(gemm_bf16, cudaFuncAttributeMaxDynamicSharedMemorySize, SMEM_DYN);

    prep_kernel<<<NPAD, 128>>>(patch);
    convert_kernel<<<MPAD / 8, 256>>>(lib);
    gemm_bf16<<<dim3(NPT, NTILES), 256, SMEM_DYN>>>();
    reduce1_kernel<<<NPT, 256>>>();
    argmax_kernel<<<1, 704>>>();
    dstar_top5<<<T5B, 256>>>();
    top5m_kernel<<<1, 256>>>();
    scalar_kernel<<<1, 192>>>(lib, out);
    resize_kernel<<<196, 256>>>();
    blurv_kernel<<<196, 256>>>();
    blurh_kernel<<<196, 256>>>(out);
}

// round 7
// speedup vs baseline: 4.7650x; 1.1267x over previous
#include <cuda_runtime.h>
#include <cuda_bf16.h>
#include <math.h>
#include <stdint.h>

#define N_PATCH 676
#define NPAD    768
#define NPT     6          // patch tiles of 128
#define D       384
#define M       200000
#define NTILES  1563       // lib tiles of 128
#define MPAD    (NTILES * 128)
#define NKB     6          // k-blocks of 64
#define IMG     224
#define KS      33
#define RAD     16
#define T5B     250        // dstar_top5 blocks

typedef unsigned long long ull;

__device__ __align__(128) __nv_bfloat16 g_libh[(size_t)MPAD * D];
__device__ __align__(16)  __nv_bfloat16 g_patchh[NPAD * D];
__device__ float g_patchN[NPAD * D];
__device__ float g_pn[NPAD];
__device__ float g_ln[MPAD];
__device__ ull   g_mink[NPAD];      // global per-patch-col min key (atomicMin)
__device__ float g_minval[N_PATCH];
__device__ float g_rmap[IMG * IMG];
__device__ float g_tmap[IMG * IMG];
__device__ int   g_sidx;
__device__ int   g_mstar;
__device__ float g_sstar;
__device__ ull   g_part[T5B * 5];
__device__ int   g_nn[5];

__device__ __forceinline__ uint32_t smem_u32(const void* p) {
    uint32_t a;
    asm("{ .reg .u64 t; cvta.to.shared.u64 t, %1; cvt.u32.u64 %0, t; }" : "=r"(a) : "l"(p));
    return a;
}
#define SW128(x) ((x) ^ (((x) >> 3) & 0x70))

#define CP16(dst, src) asm volatile("cp.async.cg.shared.global [%0], [%1], 16;" :: "r"(dst), "l"(src) : "memory")
#define CP_COMMIT()    asm volatile("cp.async.commit_group;" ::: "memory")
#define CP_WAIT1()     asm volatile("cp.async.wait_group 1;" ::: "memory")
#define CP_WAIT0()     asm volatile("cp.async.wait_group 0;" ::: "memory")

#define LDSM4(r0, r1, r2, r3, addr) \
    asm volatile("ldmatrix.sync.aligned.m8n8.x4.shared.b16 {%0,%1,%2,%3}, [%4];" \
        : "=r"(r0), "=r"(r1), "=r"(r2), "=r"(r3) : "r"(addr))

#define MMA16816(c, a, b0, b1) \
    asm volatile("mma.sync.aligned.m16n8k16.row.col.f32.bf16.bf16.f32 " \
        "{%0,%1,%2,%3}, {%4,%5,%6,%7}, {%8,%9}, {%0,%1,%2,%3};" \
        : "+f"((c)[0]), "+f"((c)[1]), "+f"((c)[2]), "+f"((c)[3]) \
        : "r"((a)[0]), "r"((a)[1]), "r"((a)[2]), "r"((a)[3]), "r"(b0), "r"(b1))

__device__ __forceinline__ unsigned f2ord(float v) {
    unsigned u = __float_as_uint(v);
    return (u & 0x80000000u) ? ~u : (u | 0x80000000u);
}
__device__ __forceinline__ float ord2f(unsigned o) {
    unsigned u = (o & 0x80000000u) ? (o & 0x7fffffffu) : ~o;
    return __uint_as_float(u);
}

__device__ __forceinline__ float dot8(uint4 a, uint4 b) {
    const unsigned* pa = (const unsigned*)&a;
    const unsigned* pb = (const unsigned*)&b;
    float s = 0.f;
#pragma unroll
    for (int i = 0; i < 4; i++) {
        float2 fa = __bfloat1622float2(*(const __nv_bfloat162*)&pa[i]);
        float2 fb = __bfloat1622float2(*(const __nv_bfloat162*)&pb[i]);
        s += fa.x * fb.x + fa.y * fb.y;
    }
    return s;
}

// ---------------- 1) normalize patch -> fp32 + bf16, pn; init g_mink ----------------
__global__ void prep_kernel(const float* __restrict__ patch) {
    int n = blockIdx.x, t = threadIdx.x;   // 128 threads
    __shared__ float red[4];
    __shared__ float bcast;
    if (t == 0) g_mink[n] = ~0ull;
    if (n >= N_PATCH) {
        for (int c = t; c < D; c += 128) {
            g_patchN[(size_t)n * D + c] = 0.f;
            g_patchh[(size_t)n * D + c] = __float2bfloat16(0.f);
        }
        if (t == 0) g_pn[n] = 0.f;
        return;
    }
    float x0 = patch[(size_t)n * D + t];
    float x1 = patch[(size_t)n * D + t + 128];
    float x2 = patch[(size_t)n * D + t + 256];
    float s = x0 * x0 + x1 * x1 + x2 * x2;
    for (int o = 16; o > 0; o >>= 1) s += __shfl_down_sync(0xffffffffu, s, o);
    if ((t & 31) == 0) red[t >> 5] = s;
    __syncthreads();
    if (t == 0) bcast = red[0] + red[1] + red[2] + red[3];
    __syncthreads();
    float inv = 1.f / fmaxf(sqrtf(bcast), 1e-12f);
    float y0 = x0 * inv, y1 = x1 * inv, y2 = x2 * inv;
    g_patchN[(size_t)n * D + t]       = y0;
    g_patchN[(size_t)n * D + t + 128] = y1;
    g_patchN[(size_t)n * D + t + 256] = y2;
    g_patchh[(size_t)n * D + t]       = __float2bfloat16(y0);
    g_patchh[(size_t)n * D + t + 128] = __float2bfloat16(y1);
    g_patchh[(size_t)n * D + t + 256] = __float2bfloat16(y2);
    float p = y0 * y0 + y1 * y1 + y2 * y2;
    for (int o = 16; o > 0; o >>= 1) p += __shfl_down_sync(0xffffffffu, p, o);
    if ((t & 31) == 0) red[t >> 5] = p;
    __syncthreads();
    if (t == 0) g_pn[n] = red[0] + red[1] + red[2] + red[3];
}

// ---------------- 2) lib fp32 -> bf16 + row norms ----------------
__global__ void convert_kernel(const float* __restrict__ lib) {
    int t = threadIdx.x, warp = t >> 5, lane = t & 31;
    long r = (long)blockIdx.x * 8 + warp;
    if (r >= MPAD) return;
    uint2* dst = (uint2*)(g_libh + (size_t)r * D);
    if (r >= M) {
        uint2 z = make_uint2(0u, 0u);
        for (int c = lane; c < 96; c += 32) dst[c] = z;
        if (lane == 0) g_ln[r] = 1e30f;
        return;
    }
    const float4* row = (const float4*)(lib + (size_t)r * D);
    float s = 0.f;
#pragma unroll
    for (int j = 0; j < 3; j++) {
        float4 v = row[lane + 32 * j];
        s += v.x * v.x + v.y * v.y + v.z * v.z + v.w * v.w;
        __nv_bfloat162 p0 = __float22bfloat162_rn(make_float2(v.x, v.y));
        __nv_bfloat162 p1 = __float22bfloat162_rn(make_float2(v.z, v.w));
        uint2 o;
        o.x = *reinterpret_cast<unsigned*>(&p0);
        o.y = *reinterpret_cast<unsigned*>(&p1);
        dst[lane + 32 * j] = o;
    }
    for (int o = 16; o > 0; o >>= 1) s += __shfl_down_sync(0xffffffffu, s, o);
    if (lane == 0) g_ln[r] = s;
}

// ---------------- 3) bf16 HMMA GEMM, 2-stage pipeline, atomic key epilogue ----------------
// As[2] @ 0/16384 (16KB each), Bs[2] @ 32768/49152. Total 64KB dyn smem.
#define SMEM_DYN 65536

__global__ void __launch_bounds__(256, 2) gemm_bf16() {
    extern __shared__ char dyn[];
    __shared__ float ln_s[128];
    __shared__ ull scmb[2][128];

    int t = threadIdx.x;
    int pt = blockIdx.x;       // patch tile (fast -> lib tile L2 reuse)
    int tile = blockIdx.y;     // lib tile
    int lane = t & 31, warp = t >> 5;
    int wm = warp >> 2, wn = warp & 3;

    uint32_t sbase = smem_u32(dyn);
    const char* gA = (const char*)g_libh + (size_t)tile * 128 * 768;
    const char* gB = (const char*)g_patchh + (size_t)pt * 128 * 768;

    if (t < 128) ln_s[t] = g_ln[(size_t)tile * 128 + t];

    // preload k-block 0
#pragma unroll
    for (int i = 0; i < 4; i++) {
        int id = i * 256 + t; int row = id >> 3, seg = id & 7;
        uint32_t off = SW128((uint32_t)(row * 128 + seg * 16));
        CP16(sbase + off, gA + (size_t)row * 768 + seg * 16);
        CP16(sbase + 32768 + off, gB + (size_t)row * 768 + seg * 16);
    }
    CP_COMMIT();

    float c[4][4][4];
#pragma unroll
    for (int mi = 0; mi < 4; mi++)
#pragma unroll
        for (int ni = 0; ni < 4; ni++)
#pragma unroll
            for (int k = 0; k < 4; k++) c[mi][ni][k] = 0.f;

    for (int kb = 0; kb < NKB; kb++) {
        int buf = kb & 1;
        if (kb < NKB - 1) {
            int nb = buf ^ 1;
            const char* ga = gA + (kb + 1) * 128;
            const char* gb = gB + (kb + 1) * 128;
#pragma unroll
            for (int i = 0; i < 4; i++) {
                int id = i * 256 + t; int row = id >> 3, seg = id & 7;
                uint32_t off = SW128((uint32_t)(row * 128 + seg * 16));
                CP16(sbase + nb * 16384 + off, ga + (size_t)row * 768 + seg * 16);
                CP16(sbase + 32768 + nb * 16384 + off, gb + (size_t)row * 768 + seg * 16);
            }
            CP_COMMIT();
            CP_WAIT1();
        } else {
            CP_WAIT0();
        }
        __syncthreads();
        uint32_t sA = sbase + buf * 16384;
        uint32_t sB = sbase + 32768 + buf * 16384;
#pragma unroll
        for (int ks = 0; ks < 4; ks++) {
            uint32_t a[4][4];
#pragma unroll
            for (int mi = 0; mi < 4; mi++) {
                uint32_t byte = (uint32_t)((wm * 64 + mi * 16 + (lane & 15)) * 128
                                           + ks * 32 + (lane >> 4) * 16);
                LDSM4(a[mi][0], a[mi][1], a[mi][2], a[mi][3], sA + SW128(byte));
            }
            uint32_t b[4][2];
#pragma unroll
            for (int nh = 0; nh < 2; nh++) {
                uint32_t byte = (uint32_t)((wn * 32 + nh * 16 + (lane & 15)) * 128
                                           + ks * 32 + (lane >> 4) * 16);
                uint32_t r0, r1, r2, r3;
                LDSM4(r0, r1, r2, r3, sB + SW128(byte));
                b[nh * 2][0] = r0; b[nh * 2 + 1][0] = r1;
                b[nh * 2][1] = r2; b[nh * 2 + 1][1] = r3;
            }
#pragma unroll
            for (int mi = 0; mi < 4; mi++)
#pragma unroll
                for (int ni = 0; ni < 4; ni++)
                    MMA16816(c[mi][ni], a[mi], b[ni][0], b[ni][1]);
        }
        __syncthreads();
    }

    // epilogue: key = (f2ord(ln - 2 dot) << 32) | lib_row ; min over 128 rows per col
    unsigned rbase = (unsigned)tile * 128u + (unsigned)(wm * 64) + (unsigned)(lane >> 2);
#pragma unroll
    for (int ni = 0; ni < 4; ni++) {
        ull k0 = ~0ull, k1 = ~0ull;
#pragma unroll
        for (int mi = 0; mi < 4; mi++) {
            int rloc = wm * 64 + mi * 16 + (lane >> 2);
            float l0 = ln_s[rloc], l1 = ln_s[rloc + 8];
            unsigned r0 = rbase + mi * 16, r1 = r0 + 8;
            float v; ull k;
            v = fmaf(-2.f, c[mi][ni][0], l0); k = ((ull)f2ord(v) << 32) | r0; k0 = min(k0, k);
            v = fmaf(-2.f, c[mi][ni][2], l1); k = ((ull)f2ord(v) << 32) | r1; k0 = min(k0, k);
            v = fmaf(-2.f, c[mi][ni][1], l0); k = ((ull)f2ord(v) << 32) | r0; k1 = min(k1, k);
            v = fmaf(-2.f, c[mi][ni][3], l1); k = ((ull)f2ord(v) << 32) | r1; k1 = min(k1, k);
        }
#pragma unroll
        for (int off = 4; off < 32; off <<= 1) {
            k0 = min(k0, __shfl_xor_sync(0xffffffffu, k0, off));
            k1 = min(k1, __shfl_xor_sync(0xffffffffu, k1, off));
        }
        if (lane < 4) {
            scmb[wm][wn * 32 + ni * 8 + lane * 2 + 0] = k0;
            scmb[wm][wn * 32 + ni * 8 + lane * 2 + 1] = k1;
        }
    }
    __syncthreads();
    if (t < 128)
        atomicMin(&g_mink[pt * 128 + t], min(scmb[0][t], scmb[1][t]));
}

// ---------------- 4) finalize minval + argmax over patch rows ----------------
__global__ void argmax_kernel() {
    int t = threadIdx.x;  // 768
    __shared__ float sv[768];
    __shared__ int si[768];
    __shared__ ull skey[768];
    float val = -3.4e38f;
    ull key = ~0ull;
    if (t < N_PATCH) {
        key = g_mink[t];
        float v = ord2f((unsigned)(key >> 32));
        val = sqrtf(fmaxf(g_pn[t] + v, 0.f));
        g_minval[t] = val;
    }
    sv[t] = val; si[t] = t; skey[t] = key;
    __syncthreads();
    for (int s = 512; s > 0; s >>= 1) {
        if (t < s && t + s < 768) {
            if (sv[t + s] > sv[t] || (sv[t + s] == sv[t] && si[t + s] < si[t])) {
                sv[t] = sv[t + s]; si[t] = si[t + s]; skey[t] = skey[t + s];
            }
        }
        __syncthreads();
    }
    if (t == 0) {
        g_sidx = si[0];
        g_sstar = sv[0];
        g_mstar = (int)(skey[0] & 0xffffffffu);
    }
}

// ---------------- 5) fused d_star + per-block top5 ----------------
__global__ void dstar_top5() {
    __shared__ uint4 q[48];
    __shared__ float smsn;
    __shared__ int sms;
    __shared__ ull wk[8][5];
    int t = threadIdx.x, warp = t >> 5, lane = t & 31;
    if (t == 0) sms = g_mstar;
    __syncthreads();
    if (t < 48) q[t] = ((const uint4*)(g_libh + (size_t)sms * D))[t];
    if (t == 63) smsn = g_ln[sms];
    __syncthreads();
    ull top[5];
#pragma unroll
    for (int k = 0; k < 5; k++) top[k] = ~0ull;
    for (int it = 0; it < 100; it++) {
        long r = (long)blockIdx.x * 800 + it * 8 + warp;
        const uint4* row = (const uint4*)(g_libh + (size_t)r * D);
        float s = dot8(row[lane], q[lane]);
        if (lane < 16) s += dot8(row[32 + lane], q[32 + lane]);
        for (int o = 16; o > 0; o >>= 1) s += __shfl_down_sync(0xffffffffu, s, o);
        if (lane == 0) {
            float d2 = g_ln[r] + smsn - 2.f * s;
            ull key = ((ull)f2ord(d2) << 32) | (unsigned)r;
            if (key < top[4]) {
                top[4] = key;
#pragma unroll
                for (int k = 4; k > 0; k--)
                    if (top[k] < top[k - 1]) { ull tv = top[k]; top[k] = top[k - 1]; top[k - 1] = tv; }
            }
        }
    }
    if (lane == 0)
#pragma unroll
        for (int k = 0; k < 5; k++) wk[warp][k] = top[k];
    __syncthreads();
    if (t == 0) {
        ull last = 0;
        for (int sel = 0; sel < 5; sel++) {
            ull best = ~0ull;
            for (int i = 0; i < 40; i++) {
                ull k = wk[i / 5][i % 5];
                if (k > last && k < best) best = k;
            }
            g_part[blockIdx.x * 5 + sel] = best;
            last = best;
        }
    }
}

// ---------------- 6) merge per-block top5 -> global top5 ----------------
__global__ void top5m_kernel() {
    __shared__ ull keys[T5B * 5];
    __shared__ ull red[256];
    int t = threadIdx.x;
    for (int i = t; i < T5B * 5; i += 256) keys[i] = g_part[i];
    __syncthreads();
    ull last = 0;
    for (int sel = 0; sel < 5; sel++) {
        ull best = ~0ull;
        for (int i = t; i < T5B * 5; i += 256) {
            ull k = keys[i];
            if (k > last && k < best) best = k;
        }
        red[t] = best;
        __syncthreads();
        for (int s = 128; s > 0; s >>= 1) {
            if (t < s) red[t] = min(red[t], red[t + s]);
            __syncthreads();
        }
        if (t == 0) g_nn[sel] = (int)(red[0] & 0xffffffffu);
        last = red[0];
        __syncthreads();
    }
}

// ---------------- 7) scalar s (fp32) ----------------
__global__ void scalar_kernel(const float* __restrict__ lib, float* __restrict__ out) {
    __shared__ float dd[6];
    __shared__ int tgt[6];
    int t = threadIdx.x, warp = t >> 5, lane = t & 31;  // 192 threads
    if (t < 5) tgt[t] = g_nn[t];
    if (t == 5) tgt[5] = g_mstar;
    __syncthreads();
    {
        long rm = tgt[warp];
        const float* p = g_patchN + (size_t)g_sidx * D;
        const float* q = lib + (size_t)rm * D;
        float s = 0.f;
        for (int c = lane; c < D; c += 32) {
            float d = p[c] - q[c];
            s += d * d;
        }
        for (int o = 16; o > 0; o >>= 1) s += __shfl_down_sync(0xffffffffu, s, o);
        if (lane == 0) dd[warp] = sqrtf(s);
    }
    __syncthreads();
    if (t == 0) {
        float den = 0.f;
        for (int k = 0; k < 5; k++) den += expf(dd[k]);
        float num = expf(dd[5]);
        out[0] = (1.f - num / den) * g_sstar;
    }
}

// ---------------- 8) bilinear 26->224 ----------------
__global__ void resize_kernel() {
    int idx = blockIdx.x * 256 + threadIdx.x;
    if (idx >= IMG * IMG) return;
    int y = idx / IMG, x = idx % IMG;
    const float scale = 26.f / 224.f;
    float fy = (y + 0.5f) * scale - 0.5f;
    float fx = (x + 0.5f) * scale - 0.5f;
    int y0 = (int)floorf(fy), x0 = (int)floorf(fx);
    float wy = fy - (float)y0, wx = fx - (float)x0;
    int y0c = min(max(y0, 0), 25), y1c = min(max(y0 + 1, 0), 25);
    int x0c = min(max(x0, 0), 25), x1c = min(max(x0 + 1, 0), 25);
    float v00 = g_minval[y0c * 26 + x0c], v01 = g_minval[y0c * 26 + x1c];
    float v10 = g_minval[y1c * 26 + x0c], v11 = g_minval[y1c * 26 + x1c];
    g_rmap[idx] = (1.f - wy) * ((1.f - wx) * v00 + wx * v01)
                + wy * ((1.f - wx) * v10 + wx * v11);
}

__device__ __forceinline__ int reflect_idx(int i) {
    if (i < 0) return -i;
    if (i > IMG - 1) return 2 * (IMG - 1) - i;
    return i;
}

// blur kernels compute unnormalized gaussian weights locally; divide sum at end
__global__ void blurv_kernel() {
    __shared__ float kw[KS];
    int t = threadIdx.x;
    if (t < KS) {
        float x = (float)(t - RAD);
        kw[t] = expf(-0.5f * (x / 4.f) * (x / 4.f));
    }
    __syncthreads();
    float wsum = 0.f;
#pragma unroll
    for (int d = 0; d < KS; d++) wsum += kw[d];
    int idx = blockIdx.x * 256 + t;
    if (idx >= IMG * IMG) return;
    int y = idx / IMG, x = idx % IMG;
    float s = 0.f;
#pragma unroll
    for (int d = 0; d < KS; d++)
        s += kw[d] * g_rmap[reflect_idx(y + d - RAD) * IMG + x];
    g_tmap[idx] = s / wsum;
}

__global__ void blurh_kernel(float* __restrict__ out) {
    __shared__ float kw[KS];
    int t = threadIdx.x;
    if (t < KS) {
        float x = (float)(t - RAD);
        kw[t] = expf(-0.5f * (x / 4.f) * (x / 4.f));
    }
    __syncthreads();
    float wsum = 0.f;
#pragma unroll
    for (int d = 0; d < KS; d++) wsum += kw[d];
    int idx = blockIdx.x * 256 + t;
    if (idx >= IMG * IMG) return;
    int y = idx / IMG, x = idx % IMG;
    float s = 0.f;
#pragma unroll
    for (int d = 0; d < KS; d++)
        s += kw[d] * g_tmap[y * IMG + reflect_idx(x + d - RAD)];
    out[1 + idx] = s / wsum;
}

// ---------------- launch ----------------
extern "C" void kernel_launch(void* const* d_in, const int* in_sizes, int n_in,
                              void* d_out, int out_size) {
    const float* patch = (const float*)d_in[0];
    const float* lib   = (const float*)d_in[1];
    if (n_in >= 2 && in_sizes[0] > in_sizes[1]) {
        const float* tmp = patch; patch = lib; lib = tmp;
    }
    float* out = (float*)d_out;

    cudaFuncSetAttribute(gemm_bf16, cudaFuncAttributeMaxDynamicSharedMemorySize, SMEM_DYN);

    prep_kernel<<<NPAD, 128>>>(patch);
    convert_kernel<<<MPAD / 8, 256>>>(lib);
    gemm_bf16<<<dim3(NPT, NTILES), 256, SMEM_DYN>>>();
    argmax_kernel<<<1, 768>>>();
    dstar_top5<<<T5B, 256>>>();
    top5m_kernel<<<1, 256>>>();
    scalar_kernel<<<1, 192>>>(lib, out);
    resize_kernel<<<196, 256>>>();
    blurv_kernel<<<196, 256>>>();
    blurh_kernel<<<196, 256>>>(out);
}